// round 1
// baseline (speedup 1.0000x reference)
#include <cuda_runtime.h>

// Problem constants
#define O_N   512
#define T_N   1024
#define HW    256     // 16x16
#define DIN   64
#define DP    64
#define HID   128
#define DOUT  128

// ---------------------------------------------------------------------------
// Scratch buffers (device globals; no runtime allocation allowed)
// ---------------------------------------------------------------------------
__device__ float g_t1 [(size_t)T_N * HID * HW];   // after block1a  (1024,128,256)
__device__ float g_t2s[(size_t)T_N * HID * HW];   // new_s raw
__device__ float g_t2o[(size_t)T_N * HID * HW];   // new_o raw
__device__ float g_pooled[(size_t)O_N * HID * HW];
__device__ float g_u  [(size_t)O_N * HID * HW];   // block(pooled, w2a)
__device__ float g_v  [(size_t)O_N * HID * HW];   // block(obj_maps, woa)

// ---------------------------------------------------------------------------
// Generic fused conv kernel.
//   KS = 3 (pad 1) or 1.  Block = (n, 16 output channels).
//   256 threads: tid&127 -> pixel pair (2p, 2p+1); tid>>7 -> co octet (0/1).
// VARIANT:
//   0 = conv1a: gather-concat input [obj_maps[s] | pred | obj_maps[o]],
//       inorm+lrelu, store to OUT (stride HID)
//   1 = conv1b: input X, 384 output chans:
//       co<128   -> raw (conv+bias) to out2 (t2s)
//       128..255 -> inorm+lrelu to OUT (d_out new_p region), channel co-128
//       co>=256  -> raw to out3 (t2o)
//   2 = plain: input X, inorm+lrelu, store to OUT (stride HID)
//   3 = plain: input X, inorm+lrelu, ADD into OUT (stride HID)
// ---------------------------------------------------------------------------
#define CB 16   // input-channel chunk

template<int CIN, int KS, int VARIANT>
__global__ void __launch_bounds__(256) conv_kernel(
    const float* __restrict__ X,
    const float* __restrict__ W,
    const float* __restrict__ B,
    float* __restrict__ OUT,
    const float* __restrict__ obj_maps,
    const float* __restrict__ pred,
    const int*   __restrict__ edges,
    float* __restrict__ out2,
    float* __restrict__ out3)
{
    constexpr int KS2 = KS * KS;
    __shared__ float s_in[CB * 324];          // CB x 18 x 18 padded tiles
    __shared__ float s_w [16 * CB * KS2];     // [ (c*KS2+t)*16 + co ]
    __shared__ float s_red[8 * 16];           // per-warp partial sums

    const int n       = blockIdx.x;
    const int co_base = blockIdx.y * 16;
    const int tid     = threadIdx.x;
    const int half    = tid >> 7;             // 0/1 -> co octet
    const int pp      = tid & 127;
    const int p0      = pp * 2;               // even pixel, same row as p0+1
    const int py      = p0 >> 4;
    const int px      = p0 & 15;
    const int lane    = tid & 31;
    const int warpId  = tid >> 5;

    int sidx = 0, oidx = 0;
    if (VARIANT == 0) { sidx = edges[2 * n]; oidx = edges[2 * n + 1]; }

    // zero smem tile once (borders stay zero; interior rewritten each chunk)
    for (int i = tid; i < CB * 324; i += 256) s_in[i] = 0.f;

    float acc[2][8];
#pragma unroll
    for (int j = 0; j < 8; j++) { acc[0][j] = 0.f; acc[1][j] = 0.f; }

    for (int ci0 = 0; ci0 < CIN; ci0 += CB) {
        __syncthreads();
        // ---- load input chunk (interior of padded tile) ----
        for (int i = tid; i < CB * HW; i += 256) {
            int c  = i >> 8;
            int p  = i & 255;
            int cg = ci0 + c;
            float v;
            if (VARIANT == 0) {
                if      (cg < DIN)     v = obj_maps[((size_t)sidx * DIN + cg) * HW + p];
                else if (cg < 2 * DIN) v = pred[(size_t)n * DP + (cg - DIN)];
                else                   v = obj_maps[((size_t)oidx * DIN + (cg - 2 * DIN)) * HW + p];
            } else {
                v = X[((size_t)n * CIN + cg) * HW + p];
            }
            int iy = p >> 4, ix = p & 15;
            s_in[c * 324 + (iy + 1) * 18 + (ix + 1)] = v;
        }
        // ---- load weight chunk ----
        for (int i = tid; i < 16 * CB * KS2; i += 256) {
            int co   = i & 15;
            int rest = i >> 4;
            int t    = rest % KS2;
            int c    = rest / KS2;
            s_w[i] = W[(((size_t)(co_base + co) * CIN) + (ci0 + c)) * KS2 + t];
        }
        __syncthreads();
        // ---- compute ----
        for (int c = 0; c < CB; c++) {
            int base = c * 324 + (py + 1) * 18 + (px + 1);
#pragma unroll
            for (int t = 0; t < KS2; t++) {
                const int dy = t / KS - KS / 2;
                const int dx = t % KS - KS / 2;
                float in0 = s_in[base + dy * 18 + dx];
                float in1 = s_in[base + dy * 18 + dx + 1];
                const float4* wp = (const float4*)(s_w + (c * KS2 + t) * 16 + half * 8);
                float4 wa = wp[0];
                float4 wb = wp[1];
                acc[0][0] += in0 * wa.x;  acc[1][0] += in1 * wa.x;
                acc[0][1] += in0 * wa.y;  acc[1][1] += in1 * wa.y;
                acc[0][2] += in0 * wa.z;  acc[1][2] += in1 * wa.z;
                acc[0][3] += in0 * wa.w;  acc[1][3] += in1 * wa.w;
                acc[0][4] += in0 * wb.x;  acc[1][4] += in1 * wb.x;
                acc[0][5] += in0 * wb.y;  acc[1][5] += in1 * wb.y;
                acc[0][6] += in0 * wb.z;  acc[1][6] += in1 * wb.z;
                acc[0][7] += in0 * wb.w;  acc[1][7] += in1 * wb.w;
            }
        }
    }

    // ---- bias ----
#pragma unroll
    for (int j = 0; j < 8; j++) {
        float bv = B[co_base + half * 8 + j];
        acc[0][j] += bv;
        acc[1][j] += bv;
    }

    // ---- does this chunk need instance-norm + lrelu? ----
    bool do_inorm;
    if (VARIANT == 1) do_inorm = (co_base >= 128 && co_base < 256);
    else              do_inorm = true;

    float mean[8], scale[8];
    if (do_inorm) {
#pragma unroll
        for (int j = 0; j < 8; j++) {
            float s  = acc[0][j] + acc[1][j];
            float ss = acc[0][j] * acc[0][j] + acc[1][j] * acc[1][j];
#pragma unroll
            for (int off = 16; off > 0; off >>= 1) {
                s  += __shfl_xor_sync(0xffffffffu, s,  off);
                ss += __shfl_xor_sync(0xffffffffu, ss, off);
            }
            if (lane == 0) {
                s_red[warpId * 16 + j * 2 + 0] = s;
                s_red[warpId * 16 + j * 2 + 1] = ss;
            }
        }
        __syncthreads();
        const int w0 = half * 4;
#pragma unroll
        for (int j = 0; j < 8; j++) {
            float S  = 0.f, SS = 0.f;
#pragma unroll
            for (int k = 0; k < 4; k++) {
                S  += s_red[(w0 + k) * 16 + j * 2 + 0];
                SS += s_red[(w0 + k) * 16 + j * 2 + 1];
            }
            float m = S * (1.f / 256.f);
            float v = SS * (1.f / 256.f) - m * m;
            mean[j]  = m;
            scale[j] = rsqrtf(v + 1e-5f);
        }
        __syncthreads();   // s_red reuse safety (none, but cheap)
    }

    // ---- finalize + store ----
#pragma unroll
    for (int j = 0; j < 8; j++) {
        int co = co_base + half * 8 + j;
        float v0 = acc[0][j];
        float v1 = acc[1][j];
        if (do_inorm) {
            v0 = (v0 - mean[j]) * scale[j];
            v1 = (v1 - mean[j]) * scale[j];
            v0 = (v0 >= 0.f) ? v0 : 0.1f * v0;
            v1 = (v1 >= 0.f) ? v1 : 0.1f * v1;
        }
        if (VARIANT == 1) {
            if (co < 128) {
                float2* dst = (float2*)(out2 + ((size_t)n * HID + co) * HW + p0);
                *dst = make_float2(v0, v1);
            } else if (co < 256) {
                float2* dst = (float2*)(OUT + ((size_t)n * HID + (co - 128)) * HW + p0);
                *dst = make_float2(v0, v1);
            } else {
                float2* dst = (float2*)(out3 + ((size_t)n * HID + (co - 256)) * HW + p0);
                *dst = make_float2(v0, v1);
            }
        } else if (VARIANT == 3) {
            float2* dst = (float2*)(OUT + ((size_t)n * HID + co) * HW + p0);
            float2 old = *dst;
            *dst = make_float2(old.x + v0, old.y + v1);
        } else {
            float2* dst = (float2*)(OUT + ((size_t)n * HID + co) * HW + p0);
            *dst = make_float2(v0, v1);
        }
    }
}

// ---------------------------------------------------------------------------
// Deterministic segment-mean pooling.
// One block per object o. Thread = pixel. Serial edge-scan builds the match
// list in fixed order (all s-matches ascending, then all o-matches), so the
// fp accumulation order is identical on every run.
// ---------------------------------------------------------------------------
__global__ void __launch_bounds__(256) pool_kernel(
    const float* __restrict__ t2s,
    const float* __restrict__ t2o,
    const int*   __restrict__ edges,
    float* __restrict__ pooled)
{
    __shared__ int es[T_N];
    __shared__ int eo[T_N];
    __shared__ int list[2 * T_N];
    __shared__ int s_cnt;

    const int o   = blockIdx.x;
    const int tid = threadIdx.x;

    for (int i = tid; i < T_N; i += 256) {
        es[i] = edges[2 * i];
        eo[i] = edges[2 * i + 1];
    }
    __syncthreads();

    if (tid == 0) {
        int c = 0;
        for (int t = 0; t < T_N; t++) if (es[t] == o) list[c++] = t * 2;
        for (int t = 0; t < T_N; t++) if (eo[t] == o) list[c++] = t * 2 + 1;
        s_cnt = c;
    }
    __syncthreads();

    const int cnt = s_cnt;
    const float inv = 1.f / (float)((cnt > 1) ? cnt : 1);

    for (int cb = 0; cb < 4; cb++) {
        float acc[32];
#pragma unroll
        for (int j = 0; j < 32; j++) acc[j] = 0.f;
        for (int m = 0; m < cnt; m++) {
            int code = list[m];
            int t    = code >> 1;
            const float* src = ((code & 1) ? t2o : t2s)
                               + ((size_t)t * HID + cb * 32) * HW + tid;
#pragma unroll
            for (int j = 0; j < 32; j++) acc[j] += src[(size_t)j * HW];
        }
#pragma unroll
        for (int j = 0; j < 32; j++)
            pooled[((size_t)o * HID + cb * 32 + j) * HW + tid] = acc[j] * inv;
    }
}

// ---------------------------------------------------------------------------
// Launch
// ---------------------------------------------------------------------------
extern "C" void kernel_launch(void* const* d_in, const int* in_sizes, int n_in,
                              void* d_out, int out_size)
{
    const float* obj_maps = (const float*)d_in[0];
    const float* pred     = (const float*)d_in[1];
    const int*   edges    = (const int*)  d_in[2];
    // d_in[3] obj_to_img: unused by the reference
    const float* w1a = (const float*)d_in[4];
    const float* b1a = (const float*)d_in[5];
    const float* w1b = (const float*)d_in[6];
    const float* b1b = (const float*)d_in[7];
    const float* w2a = (const float*)d_in[8];
    const float* b2a = (const float*)d_in[9];
    const float* w2b = (const float*)d_in[10];
    const float* b2b = (const float*)d_in[11];
    const float* woa = (const float*)d_in[12];
    const float* boa = (const float*)d_in[13];
    const float* wob = (const float*)d_in[14];
    const float* bob = (const float*)d_in[15];

    float* out_obj = (float*)d_out;                                // (512,128,16,16)
    float* out_p   = out_obj + (size_t)O_N * HID * HW;             // (1024,128,16,16)

    float *t1, *t2s, *t2o, *pooled, *u, *v;
    cudaGetSymbolAddress((void**)&t1,     g_t1);
    cudaGetSymbolAddress((void**)&t2s,    g_t2s);
    cudaGetSymbolAddress((void**)&t2o,    g_t2o);
    cudaGetSymbolAddress((void**)&pooled, g_pooled);
    cudaGetSymbolAddress((void**)&u,      g_u);
    cudaGetSymbolAddress((void**)&v,      g_v);

    // 1) t1 = block(concat(obj[s], pred, obj[o]), w1a)
    conv_kernel<192, 3, 0><<<dim3(T_N, 8), 256>>>(
        nullptr, w1a, b1a, t1, obj_maps, pred, edges, nullptr, nullptr);

    // 2) conv1b: t2s raw | new_p (inorm+lrelu -> out_p) | t2o raw
    conv_kernel<128, 3, 1><<<dim3(T_N, 24), 256>>>(
        t1, w1b, b1b, out_p, nullptr, nullptr, nullptr, t2s, t2o);

    // 3) pooled = segment-mean
    pool_kernel<<<O_N, 256>>>(t2s, t2o, edges, pooled);

    // 4) u = block(pooled, w2a) (3x3)
    conv_kernel<128, 3, 2><<<dim3(O_N, 8), 256>>>(
        pooled, w2a, b2a, u, nullptr, nullptr, nullptr, nullptr, nullptr);

    // 5) out_obj = block(u, w2b) (1x1)
    conv_kernel<128, 1, 2><<<dim3(O_N, 8), 256>>>(
        u, w2b, b2b, out_obj, nullptr, nullptr, nullptr, nullptr, nullptr);

    // 6) v = block(obj_maps, woa) (3x3)
    conv_kernel<64, 3, 2><<<dim3(O_N, 8), 256>>>(
        obj_maps, woa, boa, v, nullptr, nullptr, nullptr, nullptr, nullptr);

    // 7) out_obj += block(v, wob) (1x1)
    conv_kernel<128, 1, 3><<<dim3(O_N, 8), 256>>>(
        v, wob, bob, out_obj, nullptr, nullptr, nullptr, nullptr, nullptr);
}

// round 3
// speedup vs baseline: 1.0324x; 1.0324x over previous
#include <cuda_runtime.h>

// Problem constants
#define O_N   512
#define T_N   1024
#define HW    256     // 16x16
#define DIN   64
#define DP    64
#define HID   128
#define DOUT  128

typedef unsigned long long u64;

// ---------------------------------------------------------------------------
// Packed f32x2 helpers (sm_10x PTX)
// ---------------------------------------------------------------------------
__device__ __forceinline__ u64 dup2(float v) {
    u64 r; asm("mov.b64 %0, {%1, %1};" : "=l"(r) : "f"(v)); return r;
}
__device__ __forceinline__ void fma2(u64& d, u64 a, u64 b) {
    asm("fma.rn.f32x2 %0, %1, %2, %0;" : "+l"(d) : "l"(a), "l"(b));
}
__device__ __forceinline__ void unpack2(u64 v, float& lo, float& hi) {
    asm("mov.b64 {%0, %1}, %2;" : "=f"(lo), "=f"(hi) : "l"(v));
}

// ---------------------------------------------------------------------------
// Scratch buffers (device globals; no runtime allocation allowed)
// ---------------------------------------------------------------------------
__device__ float g_t1 [(size_t)T_N * HID * HW];   // after block1a  (1024,128,256)
__device__ float g_t2s[(size_t)T_N * HID * HW];   // new_s raw
__device__ float g_t2o[(size_t)T_N * HID * HW];   // new_o raw
__device__ float g_pooled[(size_t)O_N * HID * HW];
__device__ float g_u  [(size_t)O_N * HID * HW];   // block(pooled, w2a)
__device__ float g_v  [(size_t)O_N * HID * HW];   // block(obj_maps, woa)

// ---------------------------------------------------------------------------
// Fused conv kernel, f32x2 math.
//   Block = (n, 16 output channels). 256 threads:
//   tid>>7 -> co octet (0/1), tid&127 -> pixel pair (2p, 2p+1) on one row.
//   Accumulators: 2 pixels x 4 co-pairs (f32x2 across adjacent channels).
// VARIANT:
//   0 = conv1a: gather-concat input [obj_maps[s] | pred | obj_maps[o]],
//       inorm+lrelu -> OUT
//   1 = conv1b: 384 output chans: co<128 raw->out2; 128..255 inorm+lrelu->OUT
//       (channel co-128); co>=256 raw->out3
//   2 = plain: inorm+lrelu -> OUT
//   3 = plain: inorm+lrelu, ADD into OUT
// ---------------------------------------------------------------------------
#define CB 16   // input-channel chunk

template<int CIN, int KS, int VARIANT>
__global__ void __launch_bounds__(256) conv_kernel(
    const float* __restrict__ X,
    const float* __restrict__ W,
    const float* __restrict__ B,
    float* __restrict__ OUT,
    const float* __restrict__ obj_maps,
    const float* __restrict__ pred,
    const int*   __restrict__ edges,
    float* __restrict__ out2,
    float* __restrict__ out3)
{
    constexpr int KS2 = KS * KS;
    __shared__ __align__(16) float s_in[CB * 256];        // unpadded 16x16 tiles
    __shared__ __align__(16) float s_w [16 * CB * KS2];   // [(c*KS2+t)*16 + co]
    __shared__ float s_red[8 * 16];

    const int n       = blockIdx.x;
    const int co_base = blockIdx.y * 16;
    const int tid     = threadIdx.x;
    const int half    = tid >> 7;             // 0/1 -> co octet
    const int pp      = tid & 127;
    const int p0      = pp * 2;               // even pixel; p0+1 on same row
    const int py      = p0 >> 4;
    const int px      = p0 & 15;
    const int lane    = tid & 31;
    const int warpId  = tid >> 5;

    int sidx = 0, oidx = 0;
    if (VARIANT == 0) { sidx = edges[2 * n]; oidx = edges[2 * n + 1]; }

    u64 acc[2][4];
#pragma unroll
    for (int q = 0; q < 4; q++) { acc[0][q] = 0ull; acc[1][q] = 0ull; }

    for (int ci0 = 0; ci0 < CIN; ci0 += CB) {
        __syncthreads();
        // ---- load input chunk (raw 16x16, no padding) ----
        for (int i = tid; i < CB * HW; i += 256) {
            int c  = i >> 8;
            int p  = i & 255;
            int cg = ci0 + c;
            float v;
            if (VARIANT == 0) {
                if      (cg < DIN)     v = obj_maps[((size_t)sidx * DIN + cg) * HW + p];
                else if (cg < 2 * DIN) v = pred[(size_t)n * DP + (cg - DIN)];
                else                   v = obj_maps[((size_t)oidx * DIN + (cg - 2 * DIN)) * HW + p];
            } else {
                v = X[((size_t)n * CIN + cg) * HW + p];
            }
            s_in[c * 256 + p] = v;
        }
        // ---- load weight chunk ----
        for (int i = tid; i < 16 * CB * KS2; i += 256) {
            int co   = i & 15;
            int rest = i >> 4;
            int t    = rest % KS2;
            int c    = rest / KS2;
            s_w[i] = W[(((size_t)(co_base + co) * CIN) + (ci0 + c)) * KS2 + t];
        }
        __syncthreads();
        // ---- compute ----
        for (int c = 0; c < CB; c++) {
            const float* inb = s_in + c * 256;
#pragma unroll
            for (int r = 0; r < KS; r++) {
                u64 dv[KS + 1];
                if (KS == 3) {
                    int  ry = py + r - 1;
                    bool ok = (ry >= 0) && (ry < 16);
                    float2 mid = make_float2(0.f, 0.f);
                    if (ok) mid = *(const float2*)(inb + ry * 16 + px);
                    float v0 = (ok && px > 0)  ? inb[ry * 16 + px - 1] : 0.f;
                    float v3 = (ok && px < 14) ? inb[ry * 16 + px + 2] : 0.f;
                    dv[0] = dup2(v0);
                    dv[1] = dup2(mid.x);
                    dv[2] = dup2(mid.y);
                    dv[3] = dup2(v3);
                } else {
                    float2 mid = *(const float2*)(inb + py * 16 + px);
                    dv[0] = dup2(mid.x);
                    dv[1] = dup2(mid.y);
                }
#pragma unroll
                for (int dx = 0; dx < KS; dx++) {
                    const int t = r * KS + dx;
                    const float* wb = s_w + (c * KS2 + t) * 16 + half * 8;
                    ulonglong2 wA = *(const ulonglong2*)(wb);
                    ulonglong2 wB = *(const ulonglong2*)(wb + 4);
                    fma2(acc[0][0], dv[dx],     wA.x);
                    fma2(acc[1][0], dv[dx + 1], wA.x);
                    fma2(acc[0][1], dv[dx],     wA.y);
                    fma2(acc[1][1], dv[dx + 1], wA.y);
                    fma2(acc[0][2], dv[dx],     wB.x);
                    fma2(acc[1][2], dv[dx + 1], wB.x);
                    fma2(acc[0][3], dv[dx],     wB.y);
                    fma2(acc[1][3], dv[dx + 1], wB.y);
                }
            }
        }
    }

    // ---- unpack to scalars ----
    float a0[8], a1[8];
#pragma unroll
    for (int q = 0; q < 4; q++) {
        unpack2(acc[0][q], a0[2 * q], a0[2 * q + 1]);
        unpack2(acc[1][q], a1[2 * q], a1[2 * q + 1]);
    }

    // ---- bias ----
#pragma unroll
    for (int j = 0; j < 8; j++) {
        float bv = B[co_base + half * 8 + j];
        a0[j] += bv;
        a1[j] += bv;
    }

    // ---- does this chunk need instance-norm + lrelu? ----
    bool do_inorm;
    if (VARIANT == 1) do_inorm = (co_base >= 128 && co_base < 256);
    else              do_inorm = true;

    float mean[8], scale[8];
    if (do_inorm) {
#pragma unroll
        for (int j = 0; j < 8; j++) {
            float s  = a0[j] + a1[j];
            float ss = a0[j] * a0[j] + a1[j] * a1[j];
#pragma unroll
            for (int off = 16; off > 0; off >>= 1) {
                s  += __shfl_xor_sync(0xffffffffu, s,  off);
                ss += __shfl_xor_sync(0xffffffffu, ss, off);
            }
            if (lane == 0) {
                s_red[warpId * 16 + j * 2 + 0] = s;
                s_red[warpId * 16 + j * 2 + 1] = ss;
            }
        }
        __syncthreads();
        const int w0 = half * 4;
#pragma unroll
        for (int j = 0; j < 8; j++) {
            float S  = 0.f, SS = 0.f;
#pragma unroll
            for (int k = 0; k < 4; k++) {
                S  += s_red[(w0 + k) * 16 + j * 2 + 0];
                SS += s_red[(w0 + k) * 16 + j * 2 + 1];
            }
            float m = S * (1.f / 256.f);
            float v = SS * (1.f / 256.f) - m * m;
            mean[j]  = m;
            scale[j] = rsqrtf(v + 1e-5f);
        }
        __syncthreads();
    }

    // ---- finalize + store ----
#pragma unroll
    for (int j = 0; j < 8; j++) {
        int co = co_base + half * 8 + j;
        float v0 = a0[j];
        float v1 = a1[j];
        if (do_inorm) {
            v0 = (v0 - mean[j]) * scale[j];
            v1 = (v1 - mean[j]) * scale[j];
            v0 = (v0 >= 0.f) ? v0 : 0.1f * v0;
            v1 = (v1 >= 0.f) ? v1 : 0.1f * v1;
        }
        if (VARIANT == 1) {
            if (co < 128) {
                float2* dst = (float2*)(out2 + ((size_t)n * HID + co) * HW + p0);
                *dst = make_float2(v0, v1);
            } else if (co < 256) {
                float2* dst = (float2*)(OUT + ((size_t)n * HID + (co - 128)) * HW + p0);
                *dst = make_float2(v0, v1);
            } else {
                float2* dst = (float2*)(out3 + ((size_t)n * HID + (co - 256)) * HW + p0);
                *dst = make_float2(v0, v1);
            }
        } else if (VARIANT == 3) {
            float2* dst = (float2*)(OUT + ((size_t)n * HID + co) * HW + p0);
            float2 old = *dst;
            *dst = make_float2(old.x + v0, old.y + v1);
        } else {
            float2* dst = (float2*)(OUT + ((size_t)n * HID + co) * HW + p0);
            *dst = make_float2(v0, v1);
        }
    }
}

// ---------------------------------------------------------------------------
// Deterministic segment-mean pooling (unchanged from passing R1 kernel).
// ---------------------------------------------------------------------------
__global__ void __launch_bounds__(256) pool_kernel(
    const float* __restrict__ t2s,
    const float* __restrict__ t2o,
    const int*   __restrict__ edges,
    float* __restrict__ pooled)
{
    __shared__ int es[T_N];
    __shared__ int eo[T_N];
    __shared__ int list[2 * T_N];
    __shared__ int s_cnt;

    const int o   = blockIdx.x;
    const int tid = threadIdx.x;

    for (int i = tid; i < T_N; i += 256) {
        es[i] = edges[2 * i];
        eo[i] = edges[2 * i + 1];
    }
    __syncthreads();

    if (tid == 0) {
        int c = 0;
        for (int t = 0; t < T_N; t++) if (es[t] == o) list[c++] = t * 2;
        for (int t = 0; t < T_N; t++) if (eo[t] == o) list[c++] = t * 2 + 1;
        s_cnt = c;
    }
    __syncthreads();

    const int cnt = s_cnt;
    const float inv = 1.f / (float)((cnt > 1) ? cnt : 1);

    for (int cb = 0; cb < 4; cb++) {
        float acc[32];
#pragma unroll
        for (int j = 0; j < 32; j++) acc[j] = 0.f;
        for (int m = 0; m < cnt; m++) {
            int code = list[m];
            int t    = code >> 1;
            const float* src = ((code & 1) ? t2o : t2s)
                               + ((size_t)t * HID + cb * 32) * HW + tid;
#pragma unroll
            for (int j = 0; j < 32; j++) acc[j] += src[(size_t)j * HW];
        }
#pragma unroll
        for (int j = 0; j < 32; j++)
            pooled[((size_t)o * HID + cb * 32 + j) * HW + tid] = acc[j] * inv;
    }
}

// ---------------------------------------------------------------------------
// Launch
// ---------------------------------------------------------------------------
extern "C" void kernel_launch(void* const* d_in, const int* in_sizes, int n_in,
                              void* d_out, int out_size)
{
    const float* obj_maps = (const float*)d_in[0];
    const float* pred     = (const float*)d_in[1];
    const int*   edges    = (const int*)  d_in[2];
    // d_in[3] obj_to_img: unused by the reference
    const float* w1a = (const float*)d_in[4];
    const float* b1a = (const float*)d_in[5];
    const float* w1b = (const float*)d_in[6];
    const float* b1b = (const float*)d_in[7];
    const float* w2a = (const float*)d_in[8];
    const float* b2a = (const float*)d_in[9];
    const float* w2b = (const float*)d_in[10];
    const float* b2b = (const float*)d_in[11];
    const float* woa = (const float*)d_in[12];
    const float* boa = (const float*)d_in[13];
    const float* wob = (const float*)d_in[14];
    const float* bob = (const float*)d_in[15];

    float* out_obj = (float*)d_out;                                // (512,128,16,16)
    float* out_p   = out_obj + (size_t)O_N * HID * HW;             // (1024,128,16,16)

    float *t1, *t2s, *t2o, *pooled, *u, *v;
    cudaGetSymbolAddress((void**)&t1,     g_t1);
    cudaGetSymbolAddress((void**)&t2s,    g_t2s);
    cudaGetSymbolAddress((void**)&t2o,    g_t2o);
    cudaGetSymbolAddress((void**)&pooled, g_pooled);
    cudaGetSymbolAddress((void**)&u,      g_u);
    cudaGetSymbolAddress((void**)&v,      g_v);

    // 1) t1 = block(concat(obj[s], pred, obj[o]), w1a)
    conv_kernel<192, 3, 0><<<dim3(T_N, 8), 256>>>(
        nullptr, w1a, b1a, t1, obj_maps, pred, edges, nullptr, nullptr);

    // 2) conv1b: t2s raw | new_p (inorm+lrelu -> out_p) | t2o raw
    conv_kernel<128, 3, 1><<<dim3(T_N, 24), 256>>>(
        t1, w1b, b1b, out_p, nullptr, nullptr, nullptr, t2s, t2o);

    // 3) pooled = segment-mean
    pool_kernel<<<O_N, 256>>>(t2s, t2o, edges, pooled);

    // 4) u = block(pooled, w2a) (3x3)
    conv_kernel<128, 3, 2><<<dim3(O_N, 8), 256>>>(
        pooled, w2a, b2a, u, nullptr, nullptr, nullptr, nullptr, nullptr);

    // 5) out_obj = block(u, w2b) (1x1)
    conv_kernel<128, 1, 2><<<dim3(O_N, 8), 256>>>(
        u, w2b, b2b, out_obj, nullptr, nullptr, nullptr, nullptr, nullptr);

    // 6) v = block(obj_maps, woa) (3x3)
    conv_kernel<64, 3, 2><<<dim3(O_N, 8), 256>>>(
        obj_maps, woa, boa, v, nullptr, nullptr, nullptr, nullptr, nullptr);

    // 7) out_obj += block(v, wob) (1x1)
    conv_kernel<128, 1, 3><<<dim3(O_N, 8), 256>>>(
        v, wob, bob, out_obj, nullptr, nullptr, nullptr, nullptr, nullptr);
}

// round 5
// speedup vs baseline: 3.1937x; 3.0935x over previous
#include <cuda_runtime.h>
#include <cuda_bf16.h>
#include <cstdint>

typedef unsigned long long u64;
typedef uint32_t u32;

// Problem constants
#define O_N   512
#define T_N   1024
#define HW    256     // 16x16
#define DIN   64
#define DP    64
#define HID   128
#define DOUT  128

// ===========================================================================
// mma.sync / ldmatrix helpers (baseline PTX, valid on compute_103)
// ===========================================================================
__device__ __forceinline__ u32 smem_u32(const void* p) {
    u32 a;
    asm("{ .reg .u64 t; cvta.to.shared.u64 t, %1; cvt.u32.u64 %0, t; }" : "=r"(a) : "l"(p));
    return a;
}
__device__ __forceinline__ void ldsm4(u32* r, u32 addr) {
    asm volatile("ldmatrix.sync.aligned.m8n8.x4.shared.b16 {%0,%1,%2,%3}, [%4];"
                 : "=r"(r[0]), "=r"(r[1]), "=r"(r[2]), "=r"(r[3]) : "r"(addr));
}
__device__ __forceinline__ void mma16816(float* d, const u32* a, const u32* b) {
    asm volatile(
        "mma.sync.aligned.m16n8k16.row.col.f32.bf16.bf16.f32 "
        "{%0,%1,%2,%3}, {%4,%5,%6,%7}, {%8,%9}, {%0,%1,%2,%3};"
        : "+f"(d[0]), "+f"(d[1]), "+f"(d[2]), "+f"(d[3])
        : "r"(a[0]), "r"(a[1]), "r"(a[2]), "r"(a[3]), "r"(b[0]), "r"(b[1]));
}

// ===========================================================================
// Scratch buffers
// ===========================================================================
__device__ float g_t1 [(size_t)T_N * HID * HW];
__device__ float g_t2s[(size_t)T_N * HID * HW];
__device__ float g_t2o[(size_t)T_N * HID * HW];
__device__ float g_pooled[(size_t)O_N * HID * HW];
__device__ float g_u  [(size_t)O_N * HID * HW];
__device__ float g_v  [(size_t)O_N * HID * HW];

// Split weights (bf16 hi/lo) in padded tile layout:
// tile = (g*KS2+tap)*NCHUNK+chunk; within tile: [co(128)][72 bf16] (144B rows,
// first 64 bf16 valid = ci block, last 8 are junk-pad never read by ldmatrix k<64).
__device__ __align__(16) __nv_bfloat16 g_w1a_h[248832], g_w1a_l[248832];   // 27 tiles
__device__ __align__(16) __nv_bfloat16 g_w1b_h[497664], g_w1b_l[497664];   // 54 tiles
__device__ __align__(16) __nv_bfloat16 g_w2a_h[165888], g_w2a_l[165888];   // 18 tiles
__device__ __align__(16) __nv_bfloat16 g_w2b_h[ 18432], g_w2b_l[ 18432];   //  2 tiles
__device__ __align__(16) __nv_bfloat16 g_woa_h[ 82944], g_woa_l[ 82944];   //  9 tiles
__device__ __align__(16) __nv_bfloat16 g_wob_h[ 18432], g_wob_l[ 18432];   //  2 tiles

// ===========================================================================
// Weight prep: fp32 -> bf16 hi/lo into padded tile layout.
// W layout [co][ci][kh][kw].
// ===========================================================================
template<int CIN, int KS, int GROUPS>
__global__ void prep_kernel(const float* __restrict__ W,
                            __nv_bfloat16* __restrict__ HI,
                            __nv_bfloat16* __restrict__ LO)
{
    constexpr int KS2 = KS * KS;
    constexpr int NCHUNK = CIN / 64;
    const int total = GROUPS * 128 * CIN * KS2;
    for (int idx = blockIdx.x * blockDim.x + threadIdx.x; idx < total;
         idx += gridDim.x * blockDim.x) {
        int co  = idx / (CIN * KS2);
        int rem = idx % (CIN * KS2);
        int ci  = rem / KS2;
        int t   = rem % KS2;
        float v = W[idx];
        __nv_bfloat16 h = __float2bfloat16(v);
        __nv_bfloat16 l = __float2bfloat16(v - __bfloat162float(h));
        int g     = co >> 7;
        int chunk = ci >> 6;
        int tile  = (g * KS2 + t) * NCHUNK + chunk;
        size_t o  = (size_t)tile * 9216 + (size_t)(co & 127) * 72 + (ci & 63);
        HI[o] = h;
        LO[o] = l;
    }
}

// Zero the pad columns (ci 64..71) of every tile so nothing is garbage.
__global__ void prep_zero(__nv_bfloat16* __restrict__ P, int ntiles) {
    int idx = blockIdx.x * blockDim.x + threadIdx.x;
    int total = ntiles * 128 * 8;
    if (idx < total) {
        int tile = idx / (128 * 8);
        int rem  = idx % (128 * 8);
        int co   = rem / 8;
        int c    = rem % 8;
        P[(size_t)tile * 9216 + (size_t)co * 72 + 64 + c] = __float2bfloat16(0.f);
    }
}

// ===========================================================================
// mma.sync implicit-GEMM conv. One CTA = (image n, co-group g).
// M=128 co, N=256 px. 512 threads / 16 warps; warp tile 64x32.
// VARIANT: 0 conv1a gather+inorm | 1 conv1b (g0 raw->out2, g1 inorm->OUT,
//          g2 raw->out3) | 2 inorm->OUT | 3 inorm add->OUT
// ===========================================================================
// smem byte offsets
#define OFF_AH   0
#define OFF_AL   18432
#define OFF_XH   36864
#define OFF_XL   73872            // 36864 + 257*144 = 36864+37008
#define OFF_SUM  110880           // 73872 + 37008
#define OFF_SSQ  (110880 + 4096)
#define SMEM_SZ  (110880 + 8192)

template<int CIN, int KS, int VARIANT, int GROUPS>
__global__ void __launch_bounds__(512, 1) tconv(
    const float* __restrict__ X,
    const __nv_bfloat16* __restrict__ WHI,
    const __nv_bfloat16* __restrict__ WLO,
    const float* __restrict__ BIAS,
    float* __restrict__ OUT,
    const float* __restrict__ obj_maps,
    const float* __restrict__ pred,
    const int*   __restrict__ edges,
    float* __restrict__ out2,
    float* __restrict__ out3)
{
    constexpr int KS2 = KS * KS;
    constexpr int NCHUNK = CIN / 64;
    extern __shared__ __align__(16) char smem[];
    const u32 sb = smem_u32(smem);

    const int n    = blockIdx.x;
    const int g    = (GROUPS > 1) ? blockIdx.y : 0;
    const int tid  = threadIdx.x;
    const int lane = tid & 31;
    const int wid  = tid >> 5;
    const int wm   = wid & 1;      // 0/1 -> M 64-half
    const int wn   = wid >> 1;     // 0..7 -> N 32-slice

    int sidx = 0, oidx = 0;
    if (VARIANT == 0) { sidx = edges[2 * n]; oidx = edges[2 * n + 1]; }

    // zero rows (pixel index 256) for OOB taps
    if (tid < 36) {
        *(u32*)(smem + OFF_XH + 256 * 144 + tid * 4) = 0u;
        *(u32*)(smem + OFF_XL + 256 * 144 + tid * 4) = 0u;
    }

    float acc[4][4][4];
#pragma unroll
    for (int a = 0; a < 4; a++)
#pragma unroll
        for (int b = 0; b < 4; b++)
#pragma unroll
            for (int c = 0; c < 4; c++) acc[a][b][c] = 0.f;

    // per-lane fragment address components
    const int nl    = (lane & 7) + ((lane >> 4) & 1) * 8;  // B n-row within 16
    const int khalf = (lane >> 3) & 1;                     // B k-half
    const int ra    = wm * 64 + (lane & 15);               // A row
    const int kha   = (lane >> 4) & 1;                     // A k-half
    const u32 aBH   = sb + OFF_AH + ra * 144 + kha * 16;
    const u32 aBL   = sb + OFF_AL + ra * 144 + kha * 16;

    for (int chunk = 0; chunk < NCHUNK; chunk++) {
        __syncthreads();   // previous compute done before rewriting planes
        // ---- stage X chunk -> bf16 hi/lo planes [px][64ci], 144B rows ----
        for (int i = tid; i < 32 * 256; i += 512) {
            int cc = (i >> 8) * 2;
            int p  = i & 255;
            float v0, v1;
            if (VARIANT == 0) {
                if (chunk == 0) {
                    const float* s = obj_maps + ((size_t)sidx * DIN + cc) * HW + p;
                    v0 = s[0]; v1 = s[HW];
                } else if (chunk == 1) {
                    const float* s = pred + (size_t)n * DP + cc;
                    v0 = s[0]; v1 = s[1];
                } else {
                    const float* s = obj_maps + ((size_t)oidx * DIN + cc) * HW + p;
                    v0 = s[0]; v1 = s[HW];
                }
            } else {
                const float* s = X + ((size_t)n * CIN + chunk * 64 + cc) * HW + p;
                v0 = s[0]; v1 = s[HW];
            }
            __nv_bfloat16 h0 = __float2bfloat16(v0);
            __nv_bfloat16 h1 = __float2bfloat16(v1);
            __nv_bfloat16 l0 = __float2bfloat16(v0 - __bfloat162float(h0));
            __nv_bfloat16 l1 = __float2bfloat16(v1 - __bfloat162float(h1));
            *(__nv_bfloat162*)(smem + OFF_XH + p * 144 + cc * 2) =
                __nv_bfloat162(h0, h1);
            *(__nv_bfloat162*)(smem + OFF_XL + p * 144 + cc * 2) =
                __nv_bfloat162(l0, l1);
        }

        for (int tap = 0; tap < KS2; tap++) {
            __syncthreads();   // planes ready / A reuse safe
            // ---- stage A tile (straight copy, pre-padded layout) ----
            {
                int tile = (g * KS2 + tap) * NCHUNK + chunk;
                const int4* sh = (const int4*)(WHI + (size_t)tile * 9216);
                const int4* sl = (const int4*)(WLO + (size_t)tile * 9216);
                int4* dh = (int4*)(smem + OFF_AH);
                int4* dl = (int4*)(smem + OFF_AL);
                for (int i = tid; i < 1152; i += 512) { dh[i] = sh[i]; dl[i] = sl[i]; }
            }
            __syncthreads();

            // ---- B row pointers for this tap (shift folded into addresses) --
            const int dy = (KS == 3) ? (tap / 3 - 1) : 0;
            const int dx = (KS == 3) ? (tap % 3 - 1) : 0;
            u32 bBH[2], bBL[2];
#pragma unroll
            for (int nb = 0; nb < 2; nb++) {
                int p = wn * 32 + nb * 16 + nl;
                int y = p >> 4, x = p & 15;
                int ys = y + dy, xs = x + dx;
                u32 row = (((unsigned)ys < 16u) && ((unsigned)xs < 16u))
                              ? (u32)(ys * 16 + xs) : 256u;
                u32 off = row * 144 + khalf * 16;
                bBH[nb] = sb + OFF_XH + off;
                bBL[nb] = sb + OFF_XL + off;
            }

            // ---- compute: 4 k16 steps ----
#pragma unroll
            for (int ks = 0; ks < 4; ks++) {
                const u32 kb = ks * 32;
                u32 ah[4][4];
#pragma unroll
                for (int mt = 0; mt < 4; mt++) ldsm4(ah[mt], aBH + mt * 2304 + kb);
                u32 bh[2][4];
                ldsm4(bh[0], bBH[0] + kb);
                ldsm4(bh[1], bBH[1] + kb);
                // HH
#pragma unroll
                for (int mt = 0; mt < 4; mt++)
#pragma unroll
                    for (int nf = 0; nf < 4; nf++)
                        mma16816(acc[mt][nf], ah[mt], &bh[nf >> 1][(nf & 1) * 2]);
                // LH
                u32 al[4][4];
#pragma unroll
                for (int mt = 0; mt < 4; mt++) ldsm4(al[mt], aBL + mt * 2304 + kb);
#pragma unroll
                for (int mt = 0; mt < 4; mt++)
#pragma unroll
                    for (int nf = 0; nf < 4; nf++)
                        mma16816(acc[mt][nf], al[mt], &bh[nf >> 1][(nf & 1) * 2]);
                // HL
                u32 bl[2][4];
                ldsm4(bl[0], bBL[0] + kb);
                ldsm4(bl[1], bBL[1] + kb);
#pragma unroll
                for (int mt = 0; mt < 4; mt++)
#pragma unroll
                    for (int nf = 0; nf < 4; nf++)
                        mma16816(acc[mt][nf], ah[mt], &bl[nf >> 1][(nf & 1) * 2]);
            }
        }
    }

    // ======================= epilogue =======================
    const bool do_inorm = (VARIANT == 1) ? (g == 1) : true;
    const int q    = lane >> 2;    // 0..7
    const int csub = lane & 3;

    float* s_sum = (float*)(smem + OFF_SUM);   // [128][8]
    float* s_ssq = (float*)(smem + OFF_SSQ);

    float mean[4][2], scl[4][2], bias[4][2];

    __syncthreads();   // compute done; reuse smem for reduction

    if (do_inorm) {
#pragma unroll
        for (int mt = 0; mt < 4; mt++)
#pragma unroll
            for (int h = 0; h < 2; h++) {
                float sm = 0.f, sq = 0.f;
#pragma unroll
                for (int nf = 0; nf < 4; nf++) {
                    float v = acc[mt][nf][2 * h], w = acc[mt][nf][2 * h + 1];
                    sm += v + w;
                    sq += v * v + w * w;
                }
                sm += __shfl_xor_sync(0xffffffffu, sm, 1);
                sq += __shfl_xor_sync(0xffffffffu, sq, 1);
                sm += __shfl_xor_sync(0xffffffffu, sm, 2);
                sq += __shfl_xor_sync(0xffffffffu, sq, 2);
                if (csub == 0) {
                    int r = wm * 64 + mt * 16 + q + h * 8;
                    s_sum[r * 8 + wn] = sm;
                    s_ssq[r * 8 + wn] = sq;
                }
            }
        __syncthreads();
#pragma unroll
        for (int mt = 0; mt < 4; mt++)
#pragma unroll
            for (int h = 0; h < 2; h++) {
                int r = wm * 64 + mt * 16 + q + h * 8;
                float S = 0.f, SS = 0.f;
#pragma unroll
                for (int w = 0; w < 8; w++) { S += s_sum[r * 8 + w]; SS += s_ssq[r * 8 + w]; }
                float m = S * (1.f / 256.f);
                float var = SS * (1.f / 256.f) - m * m;
                mean[mt][h] = m;
                scl[mt][h]  = rsqrtf(var + 1e-5f);
            }
    } else {
#pragma unroll
        for (int mt = 0; mt < 4; mt++)
#pragma unroll
            for (int h = 0; h < 2; h++)
                bias[mt][h] = BIAS[g * 128 + wm * 64 + mt * 16 + q + h * 8];
    }

    // output base
    float* dst;
    if (VARIANT == 1) {
        if      (g == 0) dst = out2 + (size_t)n * HID * HW;
        else if (g == 1) dst = OUT  + (size_t)n * HID * HW;
        else             dst = out3 + (size_t)n * HID * HW;
    } else {
        dst = OUT + (size_t)n * HID * HW;
    }

#pragma unroll
    for (int mt = 0; mt < 4; mt++)
#pragma unroll
        for (int h = 0; h < 2; h++) {
            int r = wm * 64 + mt * 16 + q + h * 8;
            float* rowp = dst + (size_t)r * HW;
#pragma unroll
            for (int nf = 0; nf < 4; nf++) {
                int c = wn * 32 + nf * 8 + csub * 2;
                float v0 = acc[mt][nf][2 * h];
                float v1 = acc[mt][nf][2 * h + 1];
                if (do_inorm) {
                    v0 = (v0 - mean[mt][h]) * scl[mt][h];
                    v1 = (v1 - mean[mt][h]) * scl[mt][h];
                    v0 = (v0 >= 0.f) ? v0 : 0.1f * v0;
                    v1 = (v1 >= 0.f) ? v1 : 0.1f * v1;
                } else {
                    v0 += bias[mt][h];
                    v1 += bias[mt][h];
                }
                float2* p2 = (float2*)(rowp + c);
                if (VARIANT == 3) {
                    float2 old = *p2;
                    *p2 = make_float2(old.x + v0, old.y + v1);
                } else {
                    *p2 = make_float2(v0, v1);
                }
            }
        }
}

// ===========================================================================
// Deterministic segment-mean pooling (unchanged).
// ===========================================================================
__global__ void __launch_bounds__(256) pool_kernel(
    const float* __restrict__ t2s,
    const float* __restrict__ t2o,
    const int*   __restrict__ edges,
    float* __restrict__ pooled)
{
    __shared__ int es[T_N];
    __shared__ int eo[T_N];
    __shared__ int list[2 * T_N];
    __shared__ int s_cnt;

    const int o   = blockIdx.x;
    const int tid = threadIdx.x;

    for (int i = tid; i < T_N; i += 256) {
        es[i] = edges[2 * i];
        eo[i] = edges[2 * i + 1];
    }
    __syncthreads();

    if (tid == 0) {
        int c = 0;
        for (int t = 0; t < T_N; t++) if (es[t] == o) list[c++] = t * 2;
        for (int t = 0; t < T_N; t++) if (eo[t] == o) list[c++] = t * 2 + 1;
        s_cnt = c;
    }
    __syncthreads();

    const int cnt = s_cnt;
    const float inv = 1.f / (float)((cnt > 1) ? cnt : 1);

    for (int cb = 0; cb < 4; cb++) {
        float acc[32];
#pragma unroll
        for (int j = 0; j < 32; j++) acc[j] = 0.f;
        for (int m = 0; m < cnt; m++) {
            int code = list[m];
            int t    = code >> 1;
            const float* src = ((code & 1) ? t2o : t2s)
                               + ((size_t)t * HID + cb * 32) * HW + tid;
#pragma unroll
            for (int j = 0; j < 32; j++) acc[j] += src[(size_t)j * HW];
        }
#pragma unroll
        for (int j = 0; j < 32; j++)
            pooled[((size_t)o * HID + cb * 32 + j) * HW + tid] = acc[j] * inv;
    }
}

// ===========================================================================
// Launch
// ===========================================================================
extern "C" void kernel_launch(void* const* d_in, const int* in_sizes, int n_in,
                              void* d_out, int out_size)
{
    const float* obj_maps = (const float*)d_in[0];
    const float* pred     = (const float*)d_in[1];
    const int*   edges    = (const int*)  d_in[2];
    const float* w1a = (const float*)d_in[4];
    const float* w1b = (const float*)d_in[6];
    const float* b1b = (const float*)d_in[7];
    const float* w2a = (const float*)d_in[8];
    const float* w2b = (const float*)d_in[10];
    const float* woa = (const float*)d_in[12];
    const float* wob = (const float*)d_in[14];

    float* out_obj = (float*)d_out;
    float* out_p   = out_obj + (size_t)O_N * HID * HW;

    float *t1, *t2s, *t2o, *pooled, *u, *v;
    cudaGetSymbolAddress((void**)&t1,     g_t1);
    cudaGetSymbolAddress((void**)&t2s,    g_t2s);
    cudaGetSymbolAddress((void**)&t2o,    g_t2o);
    cudaGetSymbolAddress((void**)&pooled, g_pooled);
    cudaGetSymbolAddress((void**)&u,      g_u);
    cudaGetSymbolAddress((void**)&v,      g_v);

    __nv_bfloat16 *w1ah, *w1al, *w1bh, *w1bl, *w2ah, *w2al, *w2bh, *w2bl,
                  *woah, *woal, *wobh, *wobl;
    cudaGetSymbolAddress((void**)&w1ah, g_w1a_h); cudaGetSymbolAddress((void**)&w1al, g_w1a_l);
    cudaGetSymbolAddress((void**)&w1bh, g_w1b_h); cudaGetSymbolAddress((void**)&w1bl, g_w1b_l);
    cudaGetSymbolAddress((void**)&w2ah, g_w2a_h); cudaGetSymbolAddress((void**)&w2al, g_w2a_l);
    cudaGetSymbolAddress((void**)&w2bh, g_w2b_h); cudaGetSymbolAddress((void**)&w2bl, g_w2b_l);
    cudaGetSymbolAddress((void**)&woah, g_woa_h); cudaGetSymbolAddress((void**)&woal, g_woa_l);
    cudaGetSymbolAddress((void**)&wobh, g_wob_h); cudaGetSymbolAddress((void**)&wobl, g_wob_l);

    cudaFuncSetAttribute(tconv<192,3,0,1>, cudaFuncAttributeMaxDynamicSharedMemorySize, SMEM_SZ);
    cudaFuncSetAttribute(tconv<128,3,1,3>, cudaFuncAttributeMaxDynamicSharedMemorySize, SMEM_SZ);
    cudaFuncSetAttribute(tconv<128,3,2,1>, cudaFuncAttributeMaxDynamicSharedMemorySize, SMEM_SZ);
    cudaFuncSetAttribute(tconv<128,1,2,1>, cudaFuncAttributeMaxDynamicSharedMemorySize, SMEM_SZ);
    cudaFuncSetAttribute(tconv<64,3,2,1>,  cudaFuncAttributeMaxDynamicSharedMemorySize, SMEM_SZ);
    cudaFuncSetAttribute(tconv<128,1,3,1>, cudaFuncAttributeMaxDynamicSharedMemorySize, SMEM_SZ);

    // ---- weight prep ----
    prep_kernel<192,3,1><<<(221184+255)/256, 256>>>(w1a, w1ah, w1al);
    prep_kernel<128,3,3><<<(442368+255)/256, 256>>>(w1b, w1bh, w1bl);
    prep_kernel<128,3,1><<<(147456+255)/256, 256>>>(w2a, w2ah, w2al);
    prep_kernel<128,1,1><<<( 16384+255)/256, 256>>>(w2b, w2bh, w2bl);
    prep_kernel< 64,3,1><<<( 73728+255)/256, 256>>>(woa, woah, woal);
    prep_kernel<128,1,1><<<( 16384+255)/256, 256>>>(wob, wobh, wobl);
    prep_zero<<<(27*1024+255)/256, 256>>>(w1ah, 27);
    prep_zero<<<(27*1024+255)/256, 256>>>(w1al, 27);
    prep_zero<<<(54*1024+255)/256, 256>>>(w1bh, 54);
    prep_zero<<<(54*1024+255)/256, 256>>>(w1bl, 54);
    prep_zero<<<(18*1024+255)/256, 256>>>(w2ah, 18);
    prep_zero<<<(18*1024+255)/256, 256>>>(w2al, 18);
    prep_zero<<<( 2*1024+255)/256, 256>>>(w2bh, 2);
    prep_zero<<<( 2*1024+255)/256, 256>>>(w2bl, 2);
    prep_zero<<<( 9*1024+255)/256, 256>>>(woah, 9);
    prep_zero<<<( 9*1024+255)/256, 256>>>(woal, 9);
    prep_zero<<<( 2*1024+255)/256, 256>>>(wobh, 2);
    prep_zero<<<( 2*1024+255)/256, 256>>>(wobl, 2);

    // 1) t1 = block(concat(obj[s], pred, obj[o]), w1a)
    tconv<192,3,0,1><<<T_N, 512, SMEM_SZ>>>(
        nullptr, w1ah, w1al, nullptr, t1, obj_maps, pred, edges, nullptr, nullptr);

    // 2) conv1b: t2s raw | new_p -> out_p | t2o raw
    tconv<128,3,1,3><<<dim3(T_N, 3), 512, SMEM_SZ>>>(
        t1, w1bh, w1bl, b1b, out_p, nullptr, nullptr, nullptr, t2s, t2o);

    // 3) pooled = segment-mean
    pool_kernel<<<O_N, 256>>>(t2s, t2o, edges, pooled);

    // 4) u = block(pooled, w2a)
    tconv<128,3,2,1><<<O_N, 512, SMEM_SZ>>>(
        pooled, w2ah, w2al, nullptr, u, nullptr, nullptr, nullptr, nullptr, nullptr);

    // 5) out_obj = block(u, w2b) (1x1)
    tconv<128,1,2,1><<<O_N, 512, SMEM_SZ>>>(
        u, w2bh, w2bl, nullptr, out_obj, nullptr, nullptr, nullptr, nullptr, nullptr);

    // 6) v = block(obj_maps, woa)
    tconv<64,3,2,1><<<O_N, 512, SMEM_SZ>>>(
        obj_maps, woah, woal, nullptr, v, nullptr, nullptr, nullptr, nullptr, nullptr);

    // 7) out_obj += block(v, wob) (1x1)
    tconv<128,1,3,1><<<O_N, 512, SMEM_SZ>>>(
        v, wobh, wobl, nullptr, out_obj, nullptr, nullptr, nullptr, nullptr, nullptr);
}

// round 6
// speedup vs baseline: 4.8999x; 1.5342x over previous
#include <cuda_runtime.h>
#include <cuda_fp16.h>
#include <cstdint>

typedef unsigned long long u64;
typedef uint32_t u32;

// Problem constants
#define O_N   512
#define T_N   1024
#define HW    256     // 16x16
#define DIN   64
#define DP    64
#define HID   128
#define DOUT  128

// ===========================================================================
// mma.sync / ldmatrix / cp.async helpers (baseline PTX, valid on compute_103)
// ===========================================================================
__device__ __forceinline__ u32 smem_u32(const void* p) {
    u32 a;
    asm("{ .reg .u64 t; cvta.to.shared.u64 t, %1; cvt.u32.u64 %0, t; }" : "=r"(a) : "l"(p));
    return a;
}
__device__ __forceinline__ void ldsm4(u32* r, u32 addr) {
    asm volatile("ldmatrix.sync.aligned.m8n8.x4.shared.b16 {%0,%1,%2,%3}, [%4];"
                 : "=r"(r[0]), "=r"(r[1]), "=r"(r[2]), "=r"(r[3]) : "r"(addr));
}
__device__ __forceinline__ void mma16816(float* d, const u32* a, const u32* b) {
    asm volatile(
        "mma.sync.aligned.m16n8k16.row.col.f32.f16.f16.f32 "
        "{%0,%1,%2,%3}, {%4,%5,%6,%7}, {%8,%9}, {%0,%1,%2,%3};"
        : "+f"(d[0]), "+f"(d[1]), "+f"(d[2]), "+f"(d[3])
        : "r"(a[0]), "r"(a[1]), "r"(a[2]), "r"(a[3]), "r"(b[0]), "r"(b[1]));
}
__device__ __forceinline__ void cpa16(u32 dst, const void* src) {
    asm volatile("cp.async.cg.shared.global [%0], [%1], 16;" :: "r"(dst), "l"(src));
}
#define CP_COMMIT() asm volatile("cp.async.commit_group;" ::: "memory")
#define CP_WAIT0()  asm volatile("cp.async.wait_group 0;" ::: "memory")

// ===========================================================================
// Scratch buffers
// ===========================================================================
__device__ float g_t1 [(size_t)T_N * HID * HW];
__device__ float g_t2s[(size_t)T_N * HID * HW];
__device__ float g_t2o[(size_t)T_N * HID * HW];
__device__ float g_pooled[(size_t)O_N * HID * HW];
__device__ float g_u  [(size_t)O_N * HID * HW];
__device__ float g_v  [(size_t)O_N * HID * HW];

// fp16 weights in padded tile layout:
// tile = (g*KS2+tap)*NCHUNK+chunk; within tile: [co(128)][72 halfs] (144B rows,
// first 64 valid = ci block, last 8 zero-pad).
__device__ __align__(16) __half g_w1a[248832];   // 27 tiles
__device__ __align__(16) __half g_w1b[497664];   // 54 tiles
__device__ __align__(16) __half g_w2a[165888];   // 18 tiles
__device__ __align__(16) __half g_w2b[ 18432];   //  2 tiles
__device__ __align__(16) __half g_woa[ 82944];   //  9 tiles
__device__ __align__(16) __half g_wob[ 18432];   //  2 tiles

// ===========================================================================
// Weight prep: fp32 -> fp16 into padded tile layout. W layout [co][ci][kh][kw].
// ===========================================================================
template<int CIN, int KS, int GROUPS>
__global__ void prep_kernel(const float* __restrict__ W, __half* __restrict__ H)
{
    constexpr int KS2 = KS * KS;
    constexpr int NCHUNK = CIN / 64;
    const int total = GROUPS * 128 * CIN * KS2;
    for (int idx = blockIdx.x * blockDim.x + threadIdx.x; idx < total;
         idx += gridDim.x * blockDim.x) {
        int co  = idx / (CIN * KS2);
        int rem = idx % (CIN * KS2);
        int ci  = rem / KS2;
        int t   = rem % KS2;
        int g     = co >> 7;
        int chunk = ci >> 6;
        int tile  = (g * KS2 + t) * NCHUNK + chunk;
        size_t o  = (size_t)tile * 9216 + (size_t)(co & 127) * 72 + (ci & 63);
        H[o] = __float2half_rn(W[idx]);
    }
}

// Zero pad columns (ci 64..71) of every tile.
__global__ void prep_zero(__half* __restrict__ P, int ntiles) {
    int idx = blockIdx.x * blockDim.x + threadIdx.x;
    int total = ntiles * 128 * 8;
    if (idx < total) {
        int tile = idx / (128 * 8);
        int rem  = idx % (128 * 8);
        int co   = rem / 8;
        int c    = rem % 8;
        P[(size_t)tile * 9216 + (size_t)co * 72 + 64 + c] = __float2half_rn(0.f);
    }
}

// ===========================================================================
// mma.sync implicit-GEMM conv, fp16 2-term (W fp16, X split hi/lo fp16).
// One CTA = (image n, co-group g). M=128 co, N=256 px. 512 thr / 16 warps.
// Double-buffered A tiles via cp.async; one __syncthreads per tap.
// VARIANT: 0 conv1a gather+inorm | 1 conv1b (g0 raw->out2, g1 inorm->OUT,
//          g2 raw->out3) | 2 inorm->OUT | 3 inorm add->OUT
// ===========================================================================
// smem byte offsets
#define OFF_A0   0
#define OFF_A1   18432
#define OFF_XH   36864
#define OFF_XL   73872            // 36864 + 257*144
#define OFF_SUM  110880
#define OFF_SSQ  (110880 + 4096)
#define SMEM_SZ  (110880 + 8192)

template<int CIN, int KS, int VARIANT, int GROUPS>
__global__ void __launch_bounds__(512, 1) tconv(
    const float* __restrict__ X,
    const __half* __restrict__ WH,
    const float* __restrict__ BIAS,
    float* __restrict__ OUT,
    const float* __restrict__ obj_maps,
    const float* __restrict__ pred,
    const int*   __restrict__ edges,
    float* __restrict__ out2,
    float* __restrict__ out3)
{
    constexpr int KS2 = KS * KS;
    constexpr int NCHUNK = CIN / 64;
    extern __shared__ __align__(16) char smem[];
    const u32 sb = smem_u32(smem);

    const int n    = blockIdx.x;
    const int g    = (GROUPS > 1) ? blockIdx.y : 0;
    const int tid  = threadIdx.x;
    const int lane = tid & 31;
    const int wid  = tid >> 5;
    const int wm   = wid & 1;      // 0/1 -> M 64-half
    const int wn   = wid >> 1;     // 0..7 -> N 32-slice

    int sidx = 0, oidx = 0;
    if (VARIANT == 0) { sidx = edges[2 * n]; oidx = edges[2 * n + 1]; }

    // zero rows (pixel index 256) for OOB taps
    if (tid < 36) {
        *(u32*)(smem + OFF_XH + 256 * 144 + tid * 4) = 0u;
        *(u32*)(smem + OFF_XL + 256 * 144 + tid * 4) = 0u;
    }

    float acc[4][4][4];
#pragma unroll
    for (int a = 0; a < 4; a++)
#pragma unroll
        for (int b = 0; b < 4; b++)
#pragma unroll
            for (int c = 0; c < 4; c++) acc[a][b][c] = 0.f;

    // per-lane fragment address components
    const int nl    = (lane & 7) + ((lane >> 4) & 1) * 8;  // B n-row within 16
    const int khalf = (lane >> 3) & 1;                     // B k-half
    const int ra    = wm * 64 + (lane & 15);               // A row
    const int kha   = (lane >> 4) & 1;                     // A k-half
    const u32 aOff  = (u32)(ra * 144 + kha * 16);

    // ---- initial A prefetch (chunk 0, tap 0) into buffer 0 ----
    {
        const int4* s = (const int4*)(WH + (size_t)((g * KS2 + 0) * NCHUNK + 0) * 9216);
        for (int i = tid; i < 1152; i += 512) cpa16(sb + OFF_A0 + i * 16, s + i);
    }
    CP_COMMIT();
    int buf = 0;

    for (int chunk = 0; chunk < NCHUNK; chunk++) {
        __syncthreads();   // previous chunk compute done before rewriting planes
        // ---- stage X chunk -> fp16 hi/lo planes [px][64ci], 144B rows ----
        for (int i = tid; i < 32 * 256; i += 512) {
            int cc = (i >> 8) * 2;
            int p  = i & 255;
            float v0, v1;
            if (VARIANT == 0) {
                if (chunk == 0) {
                    const float* s = obj_maps + ((size_t)sidx * DIN + cc) * HW + p;
                    v0 = s[0]; v1 = s[HW];
                } else if (chunk == 1) {
                    const float* s = pred + (size_t)n * DP + cc;
                    v0 = s[0]; v1 = s[1];
                } else {
                    const float* s = obj_maps + ((size_t)oidx * DIN + cc) * HW + p;
                    v0 = s[0]; v1 = s[HW];
                }
            } else {
                const float* s = X + ((size_t)n * CIN + chunk * 64 + cc) * HW + p;
                v0 = s[0]; v1 = s[HW];
            }
            __half h0 = __float2half_rn(v0);
            __half h1 = __float2half_rn(v1);
            __half l0 = __float2half_rn(v0 - __half2float(h0));
            __half l1 = __float2half_rn(v1 - __half2float(h1));
            *(__half2*)(smem + OFF_XH + p * 144 + cc * 2) = __half2(h0, h1);
            *(__half2*)(smem + OFF_XL + p * 144 + cc * 2) = __half2(l0, l1);
        }

        for (int tap = 0; tap < KS2; tap++) {
            CP_WAIT0();
            __syncthreads();   // A[buf] ready, planes ready, prev compute done

            // ---- prefetch next A tile into other buffer ----
            {
                int nt = tap + 1, nc = chunk;
                if (nt == KS2) { nt = 0; nc = chunk + 1; }
                if (nc < NCHUNK) {
                    int tile = (g * KS2 + nt) * NCHUNK + nc;
                    const int4* s = (const int4*)(WH + (size_t)tile * 9216);
                    u32 d = sb + (buf ? OFF_A0 : OFF_A1);
                    for (int i = tid; i < 1152; i += 512) cpa16(d + i * 16, s + i);
                    CP_COMMIT();
                }
            }

            // ---- B row pointers for this tap (shift folded into addresses) --
            const int dy = (KS == 3) ? (tap / 3 - 1) : 0;
            const int dx = (KS == 3) ? (tap % 3 - 1) : 0;
            u32 bBH[2], bBL[2];
#pragma unroll
            for (int nb = 0; nb < 2; nb++) {
                int p = wn * 32 + nb * 16 + nl;
                int y = p >> 4, x = p & 15;
                int ys = y + dy, xs = x + dx;
                u32 row = (((unsigned)ys < 16u) && ((unsigned)xs < 16u))
                              ? (u32)(ys * 16 + xs) : 256u;
                u32 off = row * 144 + khalf * 16;
                bBH[nb] = sb + OFF_XH + off;
                bBL[nb] = sb + OFF_XL + off;
            }
            const u32 aB = sb + (buf ? OFF_A1 : OFF_A0) + aOff;

            // ---- compute: 4 k16 steps, 2 terms (W*Xh + W*Xl) ----
#pragma unroll
            for (int ks = 0; ks < 4; ks++) {
                const u32 kb = ks * 32;
                u32 a[4][4];
#pragma unroll
                for (int mt = 0; mt < 4; mt++) ldsm4(a[mt], aB + mt * 2304 + kb);
                u32 bh[2][4], bl[2][4];
                ldsm4(bh[0], bBH[0] + kb);
                ldsm4(bh[1], bBH[1] + kb);
                ldsm4(bl[0], bBL[0] + kb);
                ldsm4(bl[1], bBL[1] + kb);
#pragma unroll
                for (int mt = 0; mt < 4; mt++)
#pragma unroll
                    for (int nf = 0; nf < 4; nf++)
                        mma16816(acc[mt][nf], a[mt], &bh[nf >> 1][(nf & 1) * 2]);
#pragma unroll
                for (int mt = 0; mt < 4; mt++)
#pragma unroll
                    for (int nf = 0; nf < 4; nf++)
                        mma16816(acc[mt][nf], a[mt], &bl[nf >> 1][(nf & 1) * 2]);
            }
            buf ^= 1;
        }
    }

    // ======================= epilogue =======================
    const bool do_inorm = (VARIANT == 1) ? (g == 1) : true;
    const int q    = lane >> 2;    // 0..7
    const int csub = lane & 3;

    float* s_sum = (float*)(smem + OFF_SUM);   // [128][8]
    float* s_ssq = (float*)(smem + OFF_SSQ);

    float mean[4][2], scl[4][2], bias[4][2];

    __syncthreads();   // compute done; reuse smem for reduction

    if (do_inorm) {
#pragma unroll
        for (int mt = 0; mt < 4; mt++)
#pragma unroll
            for (int h = 0; h < 2; h++) {
                float sm = 0.f, sq = 0.f;
#pragma unroll
                for (int nf = 0; nf < 4; nf++) {
                    float v = acc[mt][nf][2 * h], w = acc[mt][nf][2 * h + 1];
                    sm += v + w;
                    sq += v * v + w * w;
                }
                sm += __shfl_xor_sync(0xffffffffu, sm, 1);
                sq += __shfl_xor_sync(0xffffffffu, sq, 1);
                sm += __shfl_xor_sync(0xffffffffu, sm, 2);
                sq += __shfl_xor_sync(0xffffffffu, sq, 2);
                if (csub == 0) {
                    int r = wm * 64 + mt * 16 + q + h * 8;
                    s_sum[r * 8 + wn] = sm;
                    s_ssq[r * 8 + wn] = sq;
                }
            }
        __syncthreads();
#pragma unroll
        for (int mt = 0; mt < 4; mt++)
#pragma unroll
            for (int h = 0; h < 2; h++) {
                int r = wm * 64 + mt * 16 + q + h * 8;
                float S = 0.f, SS = 0.f;
#pragma unroll
                for (int w = 0; w < 8; w++) { S += s_sum[r * 8 + w]; SS += s_ssq[r * 8 + w]; }
                float m = S * (1.f / 256.f);
                float var = SS * (1.f / 256.f) - m * m;
                mean[mt][h] = m;
                scl[mt][h]  = rsqrtf(var + 1e-5f);
            }
    } else {
#pragma unroll
        for (int mt = 0; mt < 4; mt++)
#pragma unroll
            for (int h = 0; h < 2; h++)
                bias[mt][h] = BIAS[g * 128 + wm * 64 + mt * 16 + q + h * 8];
    }

    // output base
    float* dst;
    if (VARIANT == 1) {
        if      (g == 0) dst = out2 + (size_t)n * HID * HW;
        else if (g == 1) dst = OUT  + (size_t)n * HID * HW;
        else             dst = out3 + (size_t)n * HID * HW;
    } else {
        dst = OUT + (size_t)n * HID * HW;
    }

#pragma unroll
    for (int mt = 0; mt < 4; mt++)
#pragma unroll
        for (int h = 0; h < 2; h++) {
            int r = wm * 64 + mt * 16 + q + h * 8;
            float* rowp = dst + (size_t)r * HW;
#pragma unroll
            for (int nf = 0; nf < 4; nf++) {
                int c = wn * 32 + nf * 8 + csub * 2;
                float v0 = acc[mt][nf][2 * h];
                float v1 = acc[mt][nf][2 * h + 1];
                if (do_inorm) {
                    v0 = (v0 - mean[mt][h]) * scl[mt][h];
                    v1 = (v1 - mean[mt][h]) * scl[mt][h];
                    v0 = (v0 >= 0.f) ? v0 : 0.1f * v0;
                    v1 = (v1 >= 0.f) ? v1 : 0.1f * v1;
                } else {
                    v0 += bias[mt][h];
                    v1 += bias[mt][h];
                }
                float2* p2 = (float2*)(rowp + c);
                if (VARIANT == 3) {
                    float2 old = *p2;
                    *p2 = make_float2(old.x + v0, old.y + v1);
                } else {
                    *p2 = make_float2(v0, v1);
                }
            }
        }
}

// ===========================================================================
// Deterministic segment-mean pooling (unchanged).
// ===========================================================================
__global__ void __launch_bounds__(256) pool_kernel(
    const float* __restrict__ t2s,
    const float* __restrict__ t2o,
    const int*   __restrict__ edges,
    float* __restrict__ pooled)
{
    __shared__ int es[T_N];
    __shared__ int eo[T_N];
    __shared__ int list[2 * T_N];
    __shared__ int s_cnt;

    const int o   = blockIdx.x;
    const int tid = threadIdx.x;

    for (int i = tid; i < T_N; i += 256) {
        es[i] = edges[2 * i];
        eo[i] = edges[2 * i + 1];
    }
    __syncthreads();

    if (tid == 0) {
        int c = 0;
        for (int t = 0; t < T_N; t++) if (es[t] == o) list[c++] = t * 2;
        for (int t = 0; t < T_N; t++) if (eo[t] == o) list[c++] = t * 2 + 1;
        s_cnt = c;
    }
    __syncthreads();

    const int cnt = s_cnt;
    const float inv = 1.f / (float)((cnt > 1) ? cnt : 1);

    for (int cb = 0; cb < 4; cb++) {
        float acc[32];
#pragma unroll
        for (int j = 0; j < 32; j++) acc[j] = 0.f;
        for (int m = 0; m < cnt; m++) {
            int code = list[m];
            int t    = code >> 1;
            const float* src = ((code & 1) ? t2o : t2s)
                               + ((size_t)t * HID + cb * 32) * HW + tid;
#pragma unroll
            for (int j = 0; j < 32; j++) acc[j] += src[(size_t)j * HW];
        }
#pragma unroll
        for (int j = 0; j < 32; j++)
            pooled[((size_t)o * HID + cb * 32 + j) * HW + tid] = acc[j] * inv;
    }
}

// ===========================================================================
// Launch
// ===========================================================================
extern "C" void kernel_launch(void* const* d_in, const int* in_sizes, int n_in,
                              void* d_out, int out_size)
{
    const float* obj_maps = (const float*)d_in[0];
    const float* pred     = (const float*)d_in[1];
    const int*   edges    = (const int*)  d_in[2];
    const float* w1a = (const float*)d_in[4];
    const float* w1b = (const float*)d_in[6];
    const float* b1b = (const float*)d_in[7];
    const float* w2a = (const float*)d_in[8];
    const float* w2b = (const float*)d_in[10];
    const float* woa = (const float*)d_in[12];
    const float* wob = (const float*)d_in[14];

    float* out_obj = (float*)d_out;
    float* out_p   = out_obj + (size_t)O_N * HID * HW;

    float *t1, *t2s, *t2o, *pooled, *u, *v;
    cudaGetSymbolAddress((void**)&t1,     g_t1);
    cudaGetSymbolAddress((void**)&t2s,    g_t2s);
    cudaGetSymbolAddress((void**)&t2o,    g_t2o);
    cudaGetSymbolAddress((void**)&pooled, g_pooled);
    cudaGetSymbolAddress((void**)&u,      g_u);
    cudaGetSymbolAddress((void**)&v,      g_v);

    __half *w1ah, *w1bh, *w2ah, *w2bh, *woah, *wobh;
    cudaGetSymbolAddress((void**)&w1ah, g_w1a);
    cudaGetSymbolAddress((void**)&w1bh, g_w1b);
    cudaGetSymbolAddress((void**)&w2ah, g_w2a);
    cudaGetSymbolAddress((void**)&w2bh, g_w2b);
    cudaGetSymbolAddress((void**)&woah, g_woa);
    cudaGetSymbolAddress((void**)&wobh, g_wob);

    cudaFuncSetAttribute(tconv<192,3,0,1>, cudaFuncAttributeMaxDynamicSharedMemorySize, SMEM_SZ);
    cudaFuncSetAttribute(tconv<128,3,1,3>, cudaFuncAttributeMaxDynamicSharedMemorySize, SMEM_SZ);
    cudaFuncSetAttribute(tconv<128,3,2,1>, cudaFuncAttributeMaxDynamicSharedMemorySize, SMEM_SZ);
    cudaFuncSetAttribute(tconv<128,1,2,1>, cudaFuncAttributeMaxDynamicSharedMemorySize, SMEM_SZ);
    cudaFuncSetAttribute(tconv<64,3,2,1>,  cudaFuncAttributeMaxDynamicSharedMemorySize, SMEM_SZ);
    cudaFuncSetAttribute(tconv<128,1,3,1>, cudaFuncAttributeMaxDynamicSharedMemorySize, SMEM_SZ);

    // ---- weight prep ----
    prep_kernel<192,3,1><<<(221184+255)/256, 256>>>(w1a, w1ah);
    prep_kernel<128,3,3><<<(442368+255)/256, 256>>>(w1b, w1bh);
    prep_kernel<128,3,1><<<(147456+255)/256, 256>>>(w2a, w2ah);
    prep_kernel<128,1,1><<<( 16384+255)/256, 256>>>(w2b, w2bh);
    prep_kernel< 64,3,1><<<( 73728+255)/256, 256>>>(woa, woah);
    prep_kernel<128,1,1><<<( 16384+255)/256, 256>>>(wob, wobh);
    prep_zero<<<(27*1024+255)/256, 256>>>(w1ah, 27);
    prep_zero<<<(54*1024+255)/256, 256>>>(w1bh, 54);
    prep_zero<<<(18*1024+255)/256, 256>>>(w2ah, 18);
    prep_zero<<<( 2*1024+255)/256, 256>>>(w2bh, 2);
    prep_zero<<<( 9*1024+255)/256, 256>>>(woah, 9);
    prep_zero<<<( 2*1024+255)/256, 256>>>(wobh, 2);

    // 1) t1 = block(concat(obj[s], pred, obj[o]), w1a)
    tconv<192,3,0,1><<<T_N, 512, SMEM_SZ>>>(
        nullptr, w1ah, nullptr, t1, obj_maps, pred, edges, nullptr, nullptr);

    // 2) conv1b: t2s raw | new_p -> out_p | t2o raw
    tconv<128,3,1,3><<<dim3(T_N, 3), 512, SMEM_SZ>>>(
        t1, w1bh, b1b, out_p, nullptr, nullptr, nullptr, t2s, t2o);

    // 3) pooled = segment-mean
    pool_kernel<<<O_N, 256>>>(t2s, t2o, edges, pooled);

    // 4) u = block(pooled, w2a)
    tconv<128,3,2,1><<<O_N, 512, SMEM_SZ>>>(
        pooled, w2ah, nullptr, u, nullptr, nullptr, nullptr, nullptr, nullptr);

    // 5) out_obj = block(u, w2b) (1x1)
    tconv<128,1,2,1><<<O_N, 512, SMEM_SZ>>>(
        u, w2bh, nullptr, out_obj, nullptr, nullptr, nullptr, nullptr, nullptr);

    // 6) v = block(obj_maps, woa)
    tconv<64,3,2,1><<<O_N, 512, SMEM_SZ>>>(
        obj_maps, woah, nullptr, v, nullptr, nullptr, nullptr, nullptr, nullptr);

    // 7) out_obj += block(v, wob) (1x1)
    tconv<128,1,3,1><<<O_N, 512, SMEM_SZ>>>(
        v, wobh, nullptr, out_obj, nullptr, nullptr, nullptr, nullptr, nullptr);
}

// round 7
// speedup vs baseline: 5.3825x; 1.0985x over previous
#include <cuda_runtime.h>
#include <cuda_fp16.h>
#include <cstdint>

typedef unsigned long long u64;
typedef uint32_t u32;

// Problem constants
#define O_N   512
#define T_N   1024
#define HW    256     // 16x16
#define DIN   64
#define DP    64
#define HID   128
#define DOUT  128

// ===========================================================================
// mma.sync / ldmatrix / cp.async helpers (baseline PTX, valid on compute_103)
// ===========================================================================
__device__ __forceinline__ u32 smem_u32(const void* p) {
    u32 a;
    asm("{ .reg .u64 t; cvta.to.shared.u64 t, %1; cvt.u32.u64 %0, t; }" : "=r"(a) : "l"(p));
    return a;
}
__device__ __forceinline__ void ldsm4(u32* r, u32 addr) {
    asm volatile("ldmatrix.sync.aligned.m8n8.x4.shared.b16 {%0,%1,%2,%3}, [%4];"
                 : "=r"(r[0]), "=r"(r[1]), "=r"(r[2]), "=r"(r[3]) : "r"(addr));
}
__device__ __forceinline__ void mma16816(float* d, const u32* a, const u32* b) {
    asm volatile(
        "mma.sync.aligned.m16n8k16.row.col.f32.f16.f16.f32 "
        "{%0,%1,%2,%3}, {%4,%5,%6,%7}, {%8,%9}, {%0,%1,%2,%3};"
        : "+f"(d[0]), "+f"(d[1]), "+f"(d[2]), "+f"(d[3])
        : "r"(a[0]), "r"(a[1]), "r"(a[2]), "r"(a[3]), "r"(b[0]), "r"(b[1]));
}
__device__ __forceinline__ void cpa16(u32 dst, const void* src) {
    asm volatile("cp.async.cg.shared.global [%0], [%1], 16;" :: "r"(dst), "l"(src));
}
#define CP_COMMIT() asm volatile("cp.async.commit_group;" ::: "memory")
#define CP_WAIT0()  asm volatile("cp.async.wait_group 0;" ::: "memory")

// ===========================================================================
// Scratch buffers
// ===========================================================================
__device__ float g_t1 [(size_t)T_N * HID * HW];
__device__ float g_ys [(size_t)O_N * HID * HW];
__device__ float g_yo [(size_t)O_N * HID * HW];
__device__ float g_T1s[(size_t)O_N * HID * HW];
__device__ float g_T1o[(size_t)O_N * HID * HW];
__device__ float g_pooled[(size_t)O_N * HID * HW];
__device__ float g_u  [(size_t)O_N * HID * HW];
__device__ float g_v  [(size_t)O_N * HID * HW];
__device__ float g_yp [(size_t)T_N * HID * 9];
__device__ float g_wc [9 * HID * 64];
__device__ float g_cnt[2 * O_N];

// fp16 weights, padded tile layout: tile = tap*NCHUNK+chunk;
// within tile: [co(128)][72 halfs] (144B rows; first 64 = ci block, last 8 zero).
__device__ __align__(16) __half g_was  [ 82944];   //  9 tiles (w1a ci 0:64)
__device__ __align__(16) __half g_wao  [ 82944];   //  9 tiles (w1a ci 128:192)
__device__ __align__(16) __half g_w1bp [165888];   // 18 tiles (w1b co 128:256)
__device__ __align__(16) __half g_w1bso[331776];   // 36 tiles (w1b s|o fused CIN=256)
__device__ __align__(16) __half g_w2a  [165888];   // 18 tiles
__device__ __align__(16) __half g_w2b  [ 18432];   //  2 tiles
__device__ __align__(16) __half g_woa  [ 82944];   //  9 tiles
__device__ __align__(16) __half g_wob  [ 18432];   //  2 tiles

// ===========================================================================
// Weight prep: slice of fp32 W [co+co_off][ci_off + c][t] -> fp16 padded tiles.
// ===========================================================================
__global__ void prep_slice(const float* __restrict__ W, __half* __restrict__ H,
                           int co_off, int ci_off, int cin_total, int ks2,
                           int nch_local, int dst_ch0, int dst_nch)
{
    int total = 128 * nch_local * 64 * ks2;
    for (int idx = blockIdx.x * blockDim.x + threadIdx.x; idx < total;
         idx += gridDim.x * blockDim.x) {
        int per_co = nch_local * 64 * ks2;
        int co  = idx / per_co;
        int rem = idx % per_co;
        int c   = rem / ks2;
        int t   = rem % ks2;
        float v = W[((size_t)(co + co_off) * cin_total + ci_off + c) * ks2 + t];
        int tile = t * dst_nch + dst_ch0 + (c >> 6);
        H[(size_t)tile * 9216 + (size_t)co * 72 + (c & 63)] = __float2half_rn(v);
    }
}

__global__ void prep_zero(__half* __restrict__ P, int ntiles) {
    int idx = blockIdx.x * blockDim.x + threadIdx.x;
    int total = ntiles * 128 * 8;
    if (idx < total) {
        int tile = idx / (128 * 8);
        int rem  = idx % (128 * 8);
        int co   = rem / 8;
        int c    = rem % 8;
        P[(size_t)tile * 9216 + (size_t)co * 72 + 64 + c] = __float2half_rn(0.f);
    }
}

// Wc[cls][co][ci] = sum of w1a[co][64+ci][tap] over taps valid for border class.
__global__ void wc_kernel(const float* __restrict__ w1a, float* __restrict__ Wc) {
    int idx = blockIdx.x * blockDim.x + threadIdx.x;
    if (idx >= 9 * 128 * 64) return;
    int cls = idx / (128 * 64);
    int co  = (idx / 64) % 128;
    int ci  = idx % 64;
    int cy = cls / 3, cx = cls % 3;
    float sum = 0.f;
    for (int ky = 0; ky < 3; ky++) {
        if ((cy == 0 && ky == 0) || (cy == 2 && ky == 2)) continue;
        for (int kx = 0; kx < 3; kx++) {
            if ((cx == 0 && kx == 0) || (cx == 2 && kx == 2)) continue;
            sum += w1a[((size_t)co * 192 + 64 + ci) * 9 + ky * 3 + kx];
        }
    }
    Wc[idx] = sum;
}

// yp[t][co*9+cls] = dot(pred[t], Wc[cls][co])
__global__ void __launch_bounds__(256) yp_kernel(
    const float* __restrict__ pred, const float* __restrict__ Wc,
    float* __restrict__ yp)
{
    __shared__ float sp[64];
    int t = blockIdx.x;
    int tid = threadIdx.x;
    if (tid < 64) sp[tid] = pred[(size_t)t * DP + tid];
    __syncthreads();
    for (int i = tid; i < 128 * 9; i += 256) {
        int co = i / 9, cls = i % 9;
        const float* wc = Wc + ((size_t)cls * 128 + co) * 64;
        float sum = 0.f;
#pragma unroll 16
        for (int ci = 0; ci < 64; ci++) sum += sp[ci] * wc[ci];
        yp[(size_t)t * 1152 + i] = sum;
    }
}

// ===========================================================================
// Combine: t1[t] = lrelu(inorm(ys[s] + yp[t] + yo[o]))  (bias cancels in inorm)
// ===========================================================================
__global__ void __launch_bounds__(256) combine_kernel(
    const float* __restrict__ ys, const float* __restrict__ yo,
    const float* __restrict__ yp, const int* __restrict__ edges,
    float* __restrict__ t1)
{
    __shared__ float s_yp[128 * 9];
    __shared__ float s_sum[128 * 8], s_ssq[128 * 8];
    __shared__ float s_mean[128], s_scl[128];
    const int t   = blockIdx.x;
    const int tid = threadIdx.x;
    const int lane = tid & 31;
    const int w    = tid >> 5;
    const int s = edges[2 * t], o = edges[2 * t + 1];

    for (int i = tid; i < 1152; i += 256) s_yp[i] = yp[(size_t)t * 1152 + i];
    __syncthreads();

    const int px = tid;
    const int y = px >> 4, x = px & 15;
    const int cy = (y == 0) ? 0 : ((y == 15) ? 2 : 1);
    const int cx = (x == 0) ? 0 : ((x == 15) ? 2 : 1);
    const int cls = cy * 3 + cx;
    const float* ysb = ys + (size_t)s * HID * HW + px;
    const float* yob = yo + (size_t)o * HID * HW + px;

    for (int ch = 0; ch < 128; ch++) {
        float val = ysb[ch * HW] + yob[ch * HW] + s_yp[ch * 9 + cls];
        float sm = val, sq = val * val;
#pragma unroll
        for (int off = 16; off > 0; off >>= 1) {
            sm += __shfl_xor_sync(0xffffffffu, sm, off);
            sq += __shfl_xor_sync(0xffffffffu, sq, off);
        }
        if (lane == 0) { s_sum[ch * 8 + w] = sm; s_ssq[ch * 8 + w] = sq; }
    }
    __syncthreads();
    if (tid < 128) {
        float S = 0.f, SS = 0.f;
#pragma unroll
        for (int k = 0; k < 8; k++) { S += s_sum[tid * 8 + k]; SS += s_ssq[tid * 8 + k]; }
        float m = S * (1.f / 256.f);
        float var = SS * (1.f / 256.f) - m * m;
        s_mean[tid] = m;
        s_scl[tid]  = rsqrtf(var + 1e-5f);
    }
    __syncthreads();
    float* dst = t1 + (size_t)t * HID * HW + px;
    for (int ch = 0; ch < 128; ch++) {
        float val = ysb[ch * HW] + yob[ch * HW] + s_yp[ch * 9 + cls];
        float vv = (val - s_mean[ch]) * s_scl[ch];
        dst[ch * HW] = (vv >= 0.f) ? vv : 0.1f * vv;
    }
}

// ===========================================================================
// Deterministic segment SUM of t1 over s-edges and o-edges, plus counts.
// ===========================================================================
__global__ void __launch_bounds__(256) pool_t1(
    const float* __restrict__ t1, const int* __restrict__ edges,
    float* __restrict__ T1s, float* __restrict__ T1o, float* __restrict__ CNT)
{
    __shared__ int es[T_N], eo[T_N];
    __shared__ int listS[T_N], listO[T_N];
    __shared__ int cS, cO;

    const int o   = blockIdx.x;
    const int tid = threadIdx.x;

    for (int i = tid; i < T_N; i += 256) {
        es[i] = edges[2 * i];
        eo[i] = edges[2 * i + 1];
    }
    __syncthreads();
    if (tid == 0) { int c = 0; for (int t = 0; t < T_N; t++) if (es[t] == o) listS[c++] = t; cS = c; }
    if (tid == 32){ int c = 0; for (int t = 0; t < T_N; t++) if (eo[t] == o) listO[c++] = t; cO = c; }
    __syncthreads();
    const int cs = cS, co = cO;

    for (int cb = 0; cb < 4; cb++) {
        float accS[32], accO[32];
#pragma unroll
        for (int j = 0; j < 32; j++) { accS[j] = 0.f; accO[j] = 0.f; }
        for (int m = 0; m < cs; m++) {
            const float* src = t1 + ((size_t)listS[m] * HID + cb * 32) * HW + tid;
#pragma unroll
            for (int j = 0; j < 32; j++) accS[j] += src[(size_t)j * HW];
        }
        for (int m = 0; m < co; m++) {
            const float* src = t1 + ((size_t)listO[m] * HID + cb * 32) * HW + tid;
#pragma unroll
            for (int j = 0; j < 32; j++) accO[j] += src[(size_t)j * HW];
        }
#pragma unroll
        for (int j = 0; j < 32; j++) {
            T1s[((size_t)o * HID + cb * 32 + j) * HW + tid] = accS[j];
            T1o[((size_t)o * HID + cb * 32 + j) * HW + tid] = accO[j];
        }
    }
    if (tid == 0) { CNT[o] = (float)cs; CNT[O_N + o] = (float)co; }
}

// ===========================================================================
// mma.sync implicit-GEMM conv, fp16 2-term (W fp16, X split hi/lo fp16).
// One CTA = image n. M=128 co, N=256 px. 512 thr / 16 warps; A double-buffered.
// VARIANT: 2 inorm->OUT | 3 inorm add->OUT | 5 dual-input pooled conv
//          (X=T1s ch<2, X2=T1o ch>=2; epi: (+cnt*bias)/max(cnt,1)) | 6 raw->OUT
// ===========================================================================
#define OFF_A0   0
#define OFF_A1   18432
#define OFF_XH   36864
#define OFF_XL   73872            // 36864 + 257*144
#define OFF_SUM  110880
#define OFF_SSQ  (110880 + 4096)
#define SMEM_SZ  (110880 + 8192)

template<int CIN, int KS, int VARIANT>
__global__ void __launch_bounds__(512, 1) tconv(
    const float* __restrict__ X,
    const float* __restrict__ X2,
    const __half* __restrict__ WH,
    const float* __restrict__ BIAS,
    const float* __restrict__ CNT,
    float* __restrict__ OUT)
{
    constexpr int KS2 = KS * KS;
    constexpr int NCHUNK = CIN / 64;
    extern __shared__ __align__(16) char smem[];
    const u32 sb = smem_u32(smem);

    const int n    = blockIdx.x;
    const int tid  = threadIdx.x;
    const int lane = tid & 31;
    const int wid  = tid >> 5;
    const int wm   = wid & 1;
    const int wn   = wid >> 1;

    // zero rows (pixel index 256) for OOB taps
    if (tid < 36) {
        *(u32*)(smem + OFF_XH + 256 * 144 + tid * 4) = 0u;
        *(u32*)(smem + OFF_XL + 256 * 144 + tid * 4) = 0u;
    }

    float acc[4][4][4];
#pragma unroll
    for (int a = 0; a < 4; a++)
#pragma unroll
        for (int b = 0; b < 4; b++)
#pragma unroll
            for (int c = 0; c < 4; c++) acc[a][b][c] = 0.f;

    const int nl    = (lane & 7) + ((lane >> 4) & 1) * 8;
    const int khalf = (lane >> 3) & 1;
    const int ra    = wm * 64 + (lane & 15);
    const int kha   = (lane >> 4) & 1;
    const u32 aOff  = (u32)(ra * 144 + kha * 16);

    // initial A prefetch (tile 0) into buffer 0
    {
        const int4* s = (const int4*)WH;
        for (int i = tid; i < 1152; i += 512) cpa16(sb + OFF_A0 + i * 16, s + i);
    }
    CP_COMMIT();
    int buf = 0;

    for (int chunk = 0; chunk < NCHUNK; chunk++) {
        __syncthreads();
        // ---- stage X chunk -> fp16 hi/lo planes [px][64ci], 144B rows ----
        for (int i = tid; i < 32 * 256; i += 512) {
            int cc = (i >> 8) * 2;
            int p  = i & 255;
            const float* s;
            if (VARIANT == 5) {
                s = (chunk < 2)
                        ? X  + ((size_t)n * 128 + chunk * 64 + cc) * HW + p
                        : X2 + ((size_t)n * 128 + (chunk - 2) * 64 + cc) * HW + p;
            } else {
                s = X + ((size_t)n * CIN + chunk * 64 + cc) * HW + p;
            }
            float v0 = s[0], v1 = s[HW];
            __half h0 = __float2half_rn(v0);
            __half h1 = __float2half_rn(v1);
            __half l0 = __float2half_rn(v0 - __half2float(h0));
            __half l1 = __float2half_rn(v1 - __half2float(h1));
            *(__half2*)(smem + OFF_XH + p * 144 + cc * 2) = __half2(h0, h1);
            *(__half2*)(smem + OFF_XL + p * 144 + cc * 2) = __half2(l0, l1);
        }

        for (int tap = 0; tap < KS2; tap++) {
            CP_WAIT0();
            __syncthreads();

            // prefetch next A tile into other buffer
            {
                int nt = tap + 1, nc = chunk;
                if (nt == KS2) { nt = 0; nc = chunk + 1; }
                if (nc < NCHUNK) {
                    const int4* s = (const int4*)(WH + (size_t)(nt * NCHUNK + nc) * 9216);
                    u32 d = sb + (buf ? OFF_A0 : OFF_A1);
                    for (int i = tid; i < 1152; i += 512) cpa16(d + i * 16, s + i);
                    CP_COMMIT();
                }
            }

            const int dy = (KS == 3) ? (tap / 3 - 1) : 0;
            const int dx = (KS == 3) ? (tap % 3 - 1) : 0;
            u32 bBH[2], bBL[2];
#pragma unroll
            for (int nb = 0; nb < 2; nb++) {
                int p = wn * 32 + nb * 16 + nl;
                int y = p >> 4, x = p & 15;
                int ys_ = y + dy, xs = x + dx;
                u32 row = (((unsigned)ys_ < 16u) && ((unsigned)xs < 16u))
                              ? (u32)(ys_ * 16 + xs) : 256u;
                u32 off = row * 144 + khalf * 16;
                bBH[nb] = sb + OFF_XH + off;
                bBL[nb] = sb + OFF_XL + off;
            }
            const u32 aB = sb + (buf ? OFF_A1 : OFF_A0) + aOff;

#pragma unroll
            for (int ks = 0; ks < 4; ks++) {
                const u32 kb = ks * 32;
                u32 a[4][4];
#pragma unroll
                for (int mt = 0; mt < 4; mt++) ldsm4(a[mt], aB + mt * 2304 + kb);
                u32 bh[2][4], bl[2][4];
                ldsm4(bh[0], bBH[0] + kb);
                ldsm4(bh[1], bBH[1] + kb);
                ldsm4(bl[0], bBL[0] + kb);
                ldsm4(bl[1], bBL[1] + kb);
#pragma unroll
                for (int mt = 0; mt < 4; mt++)
#pragma unroll
                    for (int nf = 0; nf < 4; nf++)
                        mma16816(acc[mt][nf], a[mt], &bh[nf >> 1][(nf & 1) * 2]);
#pragma unroll
                for (int mt = 0; mt < 4; mt++)
#pragma unroll
                    for (int nf = 0; nf < 4; nf++)
                        mma16816(acc[mt][nf], a[mt], &bl[nf >> 1][(nf & 1) * 2]);
            }
            buf ^= 1;
        }
    }

    // ======================= epilogue =======================
    constexpr bool do_inorm = (VARIANT == 2 || VARIANT == 3);
    const int q    = lane >> 2;
    const int csub = lane & 3;

    float* s_sum = (float*)(smem + OFF_SUM);
    float* s_ssq = (float*)(smem + OFF_SSQ);

    float mean[4][2], scl[4][2], extra[4][2];
    float inv5 = 1.f;

    __syncthreads();

    if (do_inorm) {
#pragma unroll
        for (int mt = 0; mt < 4; mt++)
#pragma unroll
            for (int h = 0; h < 2; h++) {
                float sm = 0.f, sq = 0.f;
#pragma unroll
                for (int nf = 0; nf < 4; nf++) {
                    float v = acc[mt][nf][2 * h], w = acc[mt][nf][2 * h + 1];
                    sm += v + w;
                    sq += v * v + w * w;
                }
                sm += __shfl_xor_sync(0xffffffffu, sm, 1);
                sq += __shfl_xor_sync(0xffffffffu, sq, 1);
                sm += __shfl_xor_sync(0xffffffffu, sm, 2);
                sq += __shfl_xor_sync(0xffffffffu, sq, 2);
                if (csub == 0) {
                    int r = wm * 64 + mt * 16 + q + h * 8;
                    s_sum[r * 8 + wn] = sm;
                    s_ssq[r * 8 + wn] = sq;
                }
            }
        __syncthreads();
#pragma unroll
        for (int mt = 0; mt < 4; mt++)
#pragma unroll
            for (int h = 0; h < 2; h++) {
                int r = wm * 64 + mt * 16 + q + h * 8;
                float S = 0.f, SS = 0.f;
#pragma unroll
                for (int w = 0; w < 8; w++) { S += s_sum[r * 8 + w]; SS += s_ssq[r * 8 + w]; }
                float m = S * (1.f / 256.f);
                float var = SS * (1.f / 256.f) - m * m;
                mean[mt][h] = m;
                scl[mt][h]  = rsqrtf(var + 1e-5f);
            }
    } else if (VARIANT == 5) {
        float cs = CNT[n], cf = CNT[O_N + n];
        inv5 = 1.f / fmaxf(cs + cf, 1.f);
#pragma unroll
        for (int mt = 0; mt < 4; mt++)
#pragma unroll
            for (int h = 0; h < 2; h++) {
                int r = wm * 64 + mt * 16 + q + h * 8;
                extra[mt][h] = cs * BIAS[r] + cf * BIAS[256 + r];
            }
    }

    float* dst = OUT + (size_t)n * HID * HW;

#pragma unroll
    for (int mt = 0; mt < 4; mt++)
#pragma unroll
        for (int h = 0; h < 2; h++) {
            int r = wm * 64 + mt * 16 + q + h * 8;
            float* rowp = dst + (size_t)r * HW;
#pragma unroll
            for (int nf = 0; nf < 4; nf++) {
                int c = wn * 32 + nf * 8 + csub * 2;
                float v0 = acc[mt][nf][2 * h];
                float v1 = acc[mt][nf][2 * h + 1];
                if (do_inorm) {
                    v0 = (v0 - mean[mt][h]) * scl[mt][h];
                    v1 = (v1 - mean[mt][h]) * scl[mt][h];
                    v0 = (v0 >= 0.f) ? v0 : 0.1f * v0;
                    v1 = (v1 >= 0.f) ? v1 : 0.1f * v1;
                } else if (VARIANT == 5) {
                    v0 = (v0 + extra[mt][h]) * inv5;
                    v1 = (v1 + extra[mt][h]) * inv5;
                }
                float2* p2 = (float2*)(rowp + c);
                if (VARIANT == 3) {
                    float2 old = *p2;
                    *p2 = make_float2(old.x + v0, old.y + v1);
                } else {
                    *p2 = make_float2(v0, v1);
                }
            }
        }
}

// ===========================================================================
// Launch
// ===========================================================================
extern "C" void kernel_launch(void* const* d_in, const int* in_sizes, int n_in,
                              void* d_out, int out_size)
{
    const float* obj_maps = (const float*)d_in[0];
    const float* pred     = (const float*)d_in[1];
    const int*   edges    = (const int*)  d_in[2];
    const float* w1a = (const float*)d_in[4];
    const float* w1b = (const float*)d_in[6];
    const float* b1b = (const float*)d_in[7];
    const float* w2a = (const float*)d_in[8];
    const float* w2b = (const float*)d_in[10];
    const float* woa = (const float*)d_in[12];
    const float* wob = (const float*)d_in[14];

    float* out_obj = (float*)d_out;
    float* out_p   = out_obj + (size_t)O_N * HID * HW;

    float *t1, *ys, *yo, *T1s, *T1o, *pooled, *u, *v, *yp, *wc, *cnt;
    cudaGetSymbolAddress((void**)&t1,     g_t1);
    cudaGetSymbolAddress((void**)&ys,     g_ys);
    cudaGetSymbolAddress((void**)&yo,     g_yo);
    cudaGetSymbolAddress((void**)&T1s,    g_T1s);
    cudaGetSymbolAddress((void**)&T1o,    g_T1o);
    cudaGetSymbolAddress((void**)&pooled, g_pooled);
    cudaGetSymbolAddress((void**)&u,      g_u);
    cudaGetSymbolAddress((void**)&v,      g_v);
    cudaGetSymbolAddress((void**)&yp,     g_yp);
    cudaGetSymbolAddress((void**)&wc,     g_wc);
    cudaGetSymbolAddress((void**)&cnt,    g_cnt);

    __half *was, *wao, *w1bp, *w1bso, *w2ah, *w2bh, *woah, *wobh;
    cudaGetSymbolAddress((void**)&was,   g_was);
    cudaGetSymbolAddress((void**)&wao,   g_wao);
    cudaGetSymbolAddress((void**)&w1bp,  g_w1bp);
    cudaGetSymbolAddress((void**)&w1bso, g_w1bso);
    cudaGetSymbolAddress((void**)&w2ah,  g_w2a);
    cudaGetSymbolAddress((void**)&w2bh,  g_w2b);
    cudaGetSymbolAddress((void**)&woah,  g_woa);
    cudaGetSymbolAddress((void**)&wobh,  g_wob);

    cudaFuncSetAttribute(tconv<64,3,6>,  cudaFuncAttributeMaxDynamicSharedMemorySize, SMEM_SZ);
    cudaFuncSetAttribute(tconv<128,3,2>, cudaFuncAttributeMaxDynamicSharedMemorySize, SMEM_SZ);
    cudaFuncSetAttribute(tconv<256,3,5>, cudaFuncAttributeMaxDynamicSharedMemorySize, SMEM_SZ);
    cudaFuncSetAttribute(tconv<128,1,2>, cudaFuncAttributeMaxDynamicSharedMemorySize, SMEM_SZ);
    cudaFuncSetAttribute(tconv<64,3,2>,  cudaFuncAttributeMaxDynamicSharedMemorySize, SMEM_SZ);
    cudaFuncSetAttribute(tconv<128,1,3>, cudaFuncAttributeMaxDynamicSharedMemorySize, SMEM_SZ);

    // ---- weight prep ----
    wc_kernel<<<(9*128*64 + 255) / 256, 256>>>(w1a, wc);
    prep_slice<<<288, 256>>>(w1a, was,   0,   0, 192, 9, 1, 0, 1);
    prep_slice<<<288, 256>>>(w1a, wao,   0, 128, 192, 9, 1, 0, 1);
    prep_slice<<<576, 256>>>(w1b, w1bp, 128,  0, 128, 9, 2, 0, 2);
    prep_slice<<<576, 256>>>(w1b, w1bso,  0,  0, 128, 9, 2, 0, 4);
    prep_slice<<<576, 256>>>(w1b, w1bso, 256, 0, 128, 9, 2, 2, 4);
    prep_slice<<<576, 256>>>(w2a, w2ah,   0,  0, 128, 9, 2, 0, 2);
    prep_slice<<< 64, 256>>>(w2b, w2bh,   0,  0, 128, 1, 2, 0, 2);
    prep_slice<<<288, 256>>>(woa, woah,   0,  0,  64, 9, 1, 0, 1);
    prep_slice<<< 64, 256>>>(wob, wobh,   0,  0, 128, 1, 2, 0, 2);
    prep_zero<<<(9 *1024 + 255)/256, 256>>>(was,   9);
    prep_zero<<<(9 *1024 + 255)/256, 256>>>(wao,   9);
    prep_zero<<<(18*1024 + 255)/256, 256>>>(w1bp, 18);
    prep_zero<<<(36*1024 + 255)/256, 256>>>(w1bso,36);
    prep_zero<<<(18*1024 + 255)/256, 256>>>(w2ah, 18);
    prep_zero<<<(2 *1024 + 255)/256, 256>>>(w2bh,  2);
    prep_zero<<<(9 *1024 + 255)/256, 256>>>(woah,  9);
    prep_zero<<<(2 *1024 + 255)/256, 256>>>(wobh,  2);

    // pred-part per-class GEMM
    yp_kernel<<<T_N, 256>>>(pred, wc, yp);

    // per-object convs for conv1a's s and o slices (raw, bias cancels in inorm)
    tconv<64,3,6><<<O_N, 512, SMEM_SZ>>>(obj_maps, nullptr, was, nullptr, nullptr, ys);
    tconv<64,3,6><<<O_N, 512, SMEM_SZ>>>(obj_maps, nullptr, wao, nullptr, nullptr, yo);

    // t1 = lrelu(inorm(ys[s] + yp + yo[o]))
    combine_kernel<<<T_N, 256>>>(ys, yo, yp, edges, t1);

    // new_p = lrelu(inorm(conv(t1, w1b[128:256])))  -> out_p
    tconv<128,3,2><<<T_N, 512, SMEM_SZ>>>(t1, nullptr, w1bp, nullptr, nullptr, out_p);

    // segment-sum t1 (s and o) + counts
    pool_t1<<<O_N, 256>>>(t1, edges, T1s, T1o, cnt);

    // pooled = (conv(T1s, w1b_s) + conv(T1o, w1b_o) + cnt*b)/max(cnt,1)
    tconv<256,3,5><<<O_N, 512, SMEM_SZ>>>(T1s, T1o, w1bso, b1b, cnt, pooled);

    // u = block(pooled, w2a)
    tconv<128,3,2><<<O_N, 512, SMEM_SZ>>>(pooled, nullptr, w2ah, nullptr, nullptr, u);
    // out_obj = block(u, w2b)
    tconv<128,1,2><<<O_N, 512, SMEM_SZ>>>(u, nullptr, w2bh, nullptr, nullptr, out_obj);
    // v = block(obj_maps, woa)
    tconv<64,3,2><<<O_N, 512, SMEM_SZ>>>(obj_maps, nullptr, woah, nullptr, nullptr, v);
    // out_obj += block(v, wob)
    tconv<128,1,3><<<O_N, 512, SMEM_SZ>>>(v, nullptr, wobh, nullptr, nullptr, out_obj);
}